// round 2
// baseline (speedup 1.0000x reference)
#include <cuda_runtime.h>
#include <cuda_bf16.h>

// Problem constants (fixed by the reference)
constexpr int B_ = 2048;   // batch
constexpr int Z_ = 128;    // z dim (K of layer 1)
constexpr int H_ = 1024;   // hidden
constexpr int O_ = 3072;   // output
constexpr int E_ = 8;      // experts
constexpr int MAXT = B_ / 128 + E_;  // max row tiles across experts (=24)

// Scratch (device globals; no allocations allowed)
__device__ int   g_idx[B_];
__device__ int   g_counts[E_];
__device__ int   g_offsets[E_ + 1];
__device__ int   g_cursor[E_];
__device__ int   g_perm[B_];
__device__ int   g_tile_e[MAXT];
__device__ int   g_tile_r[MAXT];
__device__ int   g_num_tiles;
__device__ float g_h[B_ * H_];   // hidden activations, indexed by ORIGINAL row

// ---------------------------------------------------------------------------
// Routing: hash = mod(sum_k floor(|z|*1000), 8). All summands are exact
// small integers in fp32 -> order-independent, bit-matches JAX.
// ---------------------------------------------------------------------------
__global__ void zero_kernel() {
    int t = threadIdx.x;
    if (t < E_) { g_counts[t] = 0; g_cursor[t] = 0; }
}

__global__ void route_kernel(const float* __restrict__ z) {
    int i = blockIdx.x * blockDim.x + threadIdx.x;
    if (i >= B_) return;
    const float* zr = z + (size_t)i * Z_;
    float s = 0.0f;
    #pragma unroll 8
    for (int k = 0; k < Z_; k++)
        s += floorf(fabsf(zr[k]) * 1000.0f);
    int e = ((int)s) & (E_ - 1);
    g_idx[i] = e;
    atomicAdd(&g_counts[e], 1);
}

__global__ void scan_kernel() {
    int o = 0, nt = 0;
    g_offsets[0] = 0;
    for (int e = 0; e < E_; e++) {
        int c = g_counts[e];
        for (int r = 0; r < c; r += 128) {
            g_tile_e[nt] = e;
            g_tile_r[nt] = r;
            nt++;
        }
        o += c;
        g_offsets[e + 1] = o;
    }
    g_num_tiles = nt;
}

__global__ void scatter_kernel() {
    int i = blockIdx.x * blockDim.x + threadIdx.x;
    if (i >= B_) return;
    int e = g_idx[i];
    int pos = g_offsets[e] + atomicAdd(&g_cursor[e], 1);
    g_perm[pos] = i;
}

// ---------------------------------------------------------------------------
// Grouped GEMM with double-buffered SMEM.
// Tile: BM=128, BN=128, BK=8. 256 threads, 8x8 micro-tile each.
// blockIdx.y indexes the compact (expert, row0) tile list.
// ---------------------------------------------------------------------------
template <bool RELU>
__global__ __launch_bounds__(256, 2)
void moe_gemm(const float* __restrict__ A, const float* __restrict__ Bw,
              const float* __restrict__ bias, float* __restrict__ C,
              int K, int N) {
    const int tile = blockIdx.y;
    if (tile >= g_num_tiles) return;
    const int e    = g_tile_e[tile];
    const int row0 = g_tile_r[tile];
    const int off  = g_offsets[e];
    const int cnt  = g_offsets[e + 1] - off;
    const int mvalid = min(128, cnt - row0);
    const int n0 = blockIdx.x * 128;

    const float* Be = Bw + (size_t)e * K * N;
    const float* be = bias + (size_t)e * N;

    __shared__ float As[2][8][129];   // [buf][k][m]
    __shared__ float Bs[2][8][128];   // [buf][k][n]
    __shared__ int   perm_s[128];

    const int t = threadIdx.x;
    if (t < 128)
        perm_s[t] = (t < mvalid) ? g_perm[off + row0 + t] : 0;
    __syncthreads();

    // Loader roles
    const int am = t >> 1;            // A: row within tile (0..127)
    const int ak = (t & 1) * 4;       // A: k offset (0 or 4)
    const int bk = t >> 5;            // B: k row (0..7)
    const int bn = (t & 31) * 4;      // B: n offset
    const bool a_ok = (am < mvalid);
    const float* Arow = A + (size_t)perm_s[am] * K + ak;
    const float* Bptr = Be + (size_t)bk * N + n0 + bn;

    const int tx = t & 15;            // n-direction (8 floats each)
    const int ty = t >> 4;            // m-direction
    float acc[8][8] = {};

    const int niter = K >> 3;

    // Stage tile 0
    float4 ra = a_ok ? *(const float4*)(Arow) : make_float4(0.f,0.f,0.f,0.f);
    float4 rb = *(const float4*)(Bptr);
    int buf = 0;
    As[0][ak + 0][am] = ra.x;
    As[0][ak + 1][am] = ra.y;
    As[0][ak + 2][am] = ra.z;
    As[0][ak + 3][am] = ra.w;
    *(float4*)&Bs[0][bk][bn] = rb;
    __syncthreads();

    for (int it = 0; it < niter; it++) {
        const bool has_next = (it + 1 < niter);
        if (has_next) {
            int k0 = (it + 1) << 3;
            ra = a_ok ? *(const float4*)(Arow + k0) : make_float4(0.f,0.f,0.f,0.f);
            rb = *(const float4*)(Bptr + (size_t)k0 * N);
        }

        #pragma unroll
        for (int kk = 0; kk < 8; kk++) {
            float a[8], b[8];
            #pragma unroll
            for (int i = 0; i < 8; i++) a[i] = As[buf][kk][ty * 8 + i];
            #pragma unroll
            for (int j = 0; j < 8; j++) b[j] = Bs[buf][kk][tx * 8 + j];
            #pragma unroll
            for (int i = 0; i < 8; i++)
                #pragma unroll
                for (int j = 0; j < 8; j++)
                    acc[i][j] += a[i] * b[j];
        }

        if (has_next) {
            int nb = buf ^ 1;
            As[nb][ak + 0][am] = ra.x;
            As[nb][ak + 1][am] = ra.y;
            As[nb][ak + 2][am] = ra.z;
            As[nb][ak + 3][am] = ra.w;
            *(float4*)&Bs[nb][bk][bn] = rb;
            __syncthreads();
            buf = nb;
        }
    }

    // Epilogue: bias (+ReLU), vectorized scatter back to original rows
    float4 bv0 = *(const float4*)(be + n0 + tx * 8);
    float4 bv1 = *(const float4*)(be + n0 + tx * 8 + 4);
    #pragma unroll
    for (int i = 0; i < 8; i++) {
        int m = ty * 8 + i;
        if (m < mvalid) {
            int orig = perm_s[m];
            float* Crow = C + (size_t)orig * N + n0 + tx * 8;
            float4 v0, v1;
            v0.x = acc[i][0] + bv0.x;  v0.y = acc[i][1] + bv0.y;
            v0.z = acc[i][2] + bv0.z;  v0.w = acc[i][3] + bv0.w;
            v1.x = acc[i][4] + bv1.x;  v1.y = acc[i][5] + bv1.y;
            v1.z = acc[i][6] + bv1.z;  v1.w = acc[i][7] + bv1.w;
            if (RELU) {
                v0.x = fmaxf(v0.x, 0.f); v0.y = fmaxf(v0.y, 0.f);
                v0.z = fmaxf(v0.z, 0.f); v0.w = fmaxf(v0.w, 0.f);
                v1.x = fmaxf(v1.x, 0.f); v1.y = fmaxf(v1.y, 0.f);
                v1.z = fmaxf(v1.z, 0.f); v1.w = fmaxf(v1.w, 0.f);
            }
            *(float4*)(Crow)     = v0;
            *(float4*)(Crow + 4) = v1;
        }
    }
}

// ---------------------------------------------------------------------------
extern "C" void kernel_launch(void* const* d_in, const int* in_sizes, int n_in,
                              void* d_out, int out_size) {
    const float* z  = (const float*)d_in[0];   // [B, Z]
    const float* W1 = (const float*)d_in[1];   // [E, Z, H]
    const float* b1 = (const float*)d_in[2];   // [E, H]
    const float* W2 = (const float*)d_in[3];   // [E, H, O]
    const float* b2 = (const float*)d_in[4];   // [E, O]
    float* out = (float*)d_out;                // [B, O]

    zero_kernel<<<1, 32>>>();
    route_kernel<<<B_ / 256, 256>>>(z);
    scan_kernel<<<1, 1>>>();
    scatter_kernel<<<B_ / 256, 256>>>();

    float* hptr;
    cudaGetSymbolAddress((void**)&hptr, g_h);

    // Layer 1: h = relu(z @ W1[e] + b1[e]);  K=128, N=1024
    {
        dim3 grid(H_ / 128, MAXT);
        moe_gemm<true><<<grid, 256>>>(z, W1, b1, hptr, Z_, H_);
    }
    // Layer 2: y = h @ W2[e] + b2[e];        K=1024, N=3072
    {
        dim3 grid(O_ / 128, MAXT);
        moe_gemm<false><<<grid, 256>>>(hptr, W2, b2, out, H_, O_);
    }
}

// round 5
// speedup vs baseline: 2.2474x; 2.2474x over previous
#include <cuda_runtime.h>
#include <cuda_bf16.h>
#include <cstdint>

// ---------------------------------------------------------------------------
constexpr int B_ = 2048, Z_ = 128, H_ = 1024, O_ = 3072, E_ = 8;
constexpr int MAXT = B_ / 128 + E_;   // 24
constexpr int BM = 128, BN = 128, BK = 32;

// SMEM layout (per stage): A hi/lo 128x32 bf16 (80B-stride rows), B hi/lo 32x128
constexpr int OFF_AH = 0;
constexpr int OFF_AL = 10240;
constexpr int OFF_BH = 20480;
constexpr int OFF_BL = 28672;
constexpr int STAGE  = 36864;
constexpr int OFF_BIAS = 2 * STAGE;          // 73728 (128 floats)
constexpr int OFF_PERM = OFF_BIAS + 512;     // 74240 (128 ints)
constexpr int SMEM_TOTAL = OFF_PERM + 512;   // 74752

// ---------------------------------------------------------------------------
__device__ int g_idx[B_], g_counts[E_], g_offsets[E_ + 1], g_cursor[E_], g_perm[B_];
__device__ int g_tile_e[MAXT], g_tile_r[MAXT], g_num_tiles;

__device__ __align__(16) __nv_bfloat16 g_zg_h[(B_ + 128) * Z_];
__device__ __align__(16) __nv_bfloat16 g_zg_l[(B_ + 128) * Z_];
__device__ __align__(16) __nv_bfloat16 g_hg_h[(B_ + 128) * H_];
__device__ __align__(16) __nv_bfloat16 g_hg_l[(B_ + 128) * H_];
__device__ __align__(16) __nv_bfloat16 g_w1_h[E_ * Z_ * H_];
__device__ __align__(16) __nv_bfloat16 g_w1_l[E_ * Z_ * H_];
__device__ __align__(16) __nv_bfloat16 g_w2_h[(size_t)E_ * H_ * O_];
__device__ __align__(16) __nv_bfloat16 g_w2_l[(size_t)E_ * H_ * O_];

// ---------------------------------------------------------------------------
// PTX helpers (all arch-agnostic: sm_80+ instructions only)
// ---------------------------------------------------------------------------
__device__ __forceinline__ uint32_t smem_u32(const void* p) {
    return (uint32_t)__cvta_generic_to_shared(p);
}
__device__ __forceinline__ void cp16(uint32_t dst, const void* src) {
    asm volatile("cp.async.cg.shared.global [%0], [%1], 16;" :: "r"(dst), "l"(src) : "memory");
}
__device__ __forceinline__ void cp_commit() {
    asm volatile("cp.async.commit_group;" ::: "memory");
}
__device__ __forceinline__ void cp_wait1() {
    asm volatile("cp.async.wait_group 1;" ::: "memory");
}
__device__ __forceinline__ void ldsm4(uint32_t* r, uint32_t a) {
    asm volatile("ldmatrix.sync.aligned.m8n8.x4.shared.b16 {%0,%1,%2,%3}, [%4];"
                 : "=r"(r[0]), "=r"(r[1]), "=r"(r[2]), "=r"(r[3]) : "r"(a));
}
__device__ __forceinline__ void ldsm4t(uint32_t* r, uint32_t a) {
    asm volatile("ldmatrix.sync.aligned.m8n8.x4.trans.shared.b16 {%0,%1,%2,%3}, [%4];"
                 : "=r"(r[0]), "=r"(r[1]), "=r"(r[2]), "=r"(r[3]) : "r"(a));
}
__device__ __forceinline__ void mma16816(float* d, const uint32_t* a, uint32_t b0, uint32_t b1) {
    asm volatile(
        "mma.sync.aligned.m16n8k16.row.col.f32.bf16.bf16.f32 "
        "{%0,%1,%2,%3}, {%4,%5,%6,%7}, {%8,%9}, {%0,%1,%2,%3};"
        : "+f"(d[0]), "+f"(d[1]), "+f"(d[2]), "+f"(d[3])
        : "r"(a[0]), "r"(a[1]), "r"(a[2]), "r"(a[3]), "r"(b0), "r"(b1));
}

// ---------------------------------------------------------------------------
// Routing (bit-exact vs JAX: exact small integers in fp32, order-independent)
// ---------------------------------------------------------------------------
__global__ void zero_kernel() {
    int t = threadIdx.x;
    if (t < E_) { g_counts[t] = 0; g_cursor[t] = 0; }
}
__global__ void route_kernel(const float* __restrict__ z) {
    int i = blockIdx.x * blockDim.x + threadIdx.x;
    if (i >= B_) return;
    const float* zr = z + (size_t)i * Z_;
    float s = 0.0f;
    #pragma unroll 8
    for (int k = 0; k < Z_; k++)
        s += floorf(fabsf(zr[k]) * 1000.0f);
    int e = ((int)s) & (E_ - 1);
    g_idx[i] = e;
    atomicAdd(&g_counts[e], 1);
}
__global__ void scan_kernel() {
    int o = 0, nt = 0;
    g_offsets[0] = 0;
    for (int e = 0; e < E_; e++) {
        int c = g_counts[e];
        for (int r = 0; r < c; r += BM) { g_tile_e[nt] = e; g_tile_r[nt] = r; nt++; }
        o += c;
        g_offsets[e + 1] = o;
    }
    g_num_tiles = nt;
}
__global__ void scatter_kernel() {
    int i = blockIdx.x * blockDim.x + threadIdx.x;
    if (i >= B_) return;
    int e = g_idx[i];
    int pos = g_offsets[e] + atomicAdd(&g_cursor[e], 1);
    g_perm[pos] = i;
}

// ---------------------------------------------------------------------------
// Conversions
// ---------------------------------------------------------------------------
__global__ void gather_split_z(const float* __restrict__ z) {
    int idx = blockIdx.x * blockDim.x + threadIdx.x;
    if (idx >= B_ * Z_) return;
    int p = idx >> 7;                   // Z_ = 128
    int k = idx & (Z_ - 1);
    float v = z[(size_t)g_perm[p] * Z_ + k];
    __nv_bfloat16 h = __float2bfloat16(v);
    g_zg_h[idx] = h;
    g_zg_l[idx] = __float2bfloat16(v - __bfloat162float(h));
}

// Elementwise fp32 -> bf16 hi/lo split (same layout, no transpose)
__global__ void split_w(const float4* __restrict__ src,
                        __nv_bfloat162* __restrict__ dh,
                        __nv_bfloat162* __restrict__ dl, int n4) {
    int i = blockIdx.x * blockDim.x + threadIdx.x;
    if (i >= n4) return;
    float4 v = src[i];
    __nv_bfloat16 h0 = __float2bfloat16(v.x), h1 = __float2bfloat16(v.y);
    __nv_bfloat16 h2 = __float2bfloat16(v.z), h3 = __float2bfloat16(v.w);
    __nv_bfloat16 l0 = __float2bfloat16(v.x - __bfloat162float(h0));
    __nv_bfloat16 l1 = __float2bfloat16(v.y - __bfloat162float(h1));
    __nv_bfloat16 l2 = __float2bfloat16(v.z - __bfloat162float(h2));
    __nv_bfloat16 l3 = __float2bfloat16(v.w - __bfloat162float(h3));
    dh[2 * i]     = __nv_bfloat162(h0, h1);
    dh[2 * i + 1] = __nv_bfloat162(h2, h3);
    dl[2 * i]     = __nv_bfloat162(l0, l1);
    dl[2 * i + 1] = __nv_bfloat162(l2, l3);
}

// ---------------------------------------------------------------------------
// mma.sync grouped GEMM: C[128x128] tile = A[128xK] (perm rows) * B[K x NTOT]
// 3-term bf16 split: AhBh + AhBl + AlBh, fp32 accumulate.
// MODE 0: relu(x+bias) -> bf16 hi/lo stores (perm-order rows)
// MODE 1: x+bias -> fp32 scatter to original rows via perm
// ---------------------------------------------------------------------------
template <int MODE>
__global__ __launch_bounds__(256, 1)
void moe_mma(const __nv_bfloat16* __restrict__ Ah, const __nv_bfloat16* __restrict__ Al,
             const __nv_bfloat16* __restrict__ Bh, const __nv_bfloat16* __restrict__ Bl,
             const float* __restrict__ bias,
             __nv_bfloat16* __restrict__ oh, __nv_bfloat16* __restrict__ ol,
             float* __restrict__ outf, int K, int NTOT) {
    const int tile = blockIdx.y;
    if (tile >= g_num_tiles) return;
    const int e      = g_tile_e[tile];
    const int row0   = g_tile_r[tile];
    const int off    = g_offsets[e];
    const int cnt    = g_offsets[e + 1] - off;
    const int mvalid = min(BM, cnt - row0);
    const int n0     = blockIdx.x * BN;
    const int arow0  = off + row0;

    extern __shared__ char smem[];
    const uint32_t sb = smem_u32(smem);
    float* sBias = (float*)(smem + OFF_BIAS);
    int*   sPerm = (int*)(smem + OFF_PERM);

    const int t = threadIdx.x;
    const int lane = t & 31;
    const int wid = t >> 5;

    if (t < 128) {
        sBias[t] = bias[(size_t)e * NTOT + n0 + t];
        if (MODE == 1) sPerm[t] = (t < mvalid) ? g_perm[arow0 + t] : 0;
    }

    const __nv_bfloat16* BhE = Bh + (size_t)e * NTOT * K;
    const __nv_bfloat16* BlE = Bl + (size_t)e * NTOT * K;
    const int NS = K / BK;

    auto load_stage = [&](int s) {
        const int k0 = s * BK;
        const uint32_t base = sb + (s & 1) * STAGE;
        #pragma unroll
        for (int i = 0; i < 2; i++) {               // A: 512 chunks of 16B (hi+lo)
            int idx = t + i * 256;
            int r = idx >> 2, kc = idx & 3;
            uint32_t d = (uint32_t)(r * 80 + kc * 16);
            size_t so = (size_t)(arow0 + r) * K + k0 + kc * 8;
            cp16(base + OFF_AH + d, Ah + so);
            cp16(base + OFF_AL + d, Al + so);
        }
        #pragma unroll
        for (int i = 0; i < 2; i++) {               // B: 512 chunks of 16B (hi+lo)
            int idx = t + i * 256;
            int kr = idx >> 4, nc = idx & 15;       // kr 0..31, nc 0..15
            uint32_t d = (uint32_t)(kr * 256 + nc * 16) ^ (uint32_t)((kr & 15) << 4);
            size_t so = (size_t)(k0 + kr) * NTOT + n0 + nc * 8;
            cp16(base + OFF_BH + d, BhE + so);
            cp16(base + OFF_BL + d, BlE + so);
        }
        cp_commit();
    };

    const int wm0 = (wid & 3) * 32;   // 4 warps along M
    const int wn0 = (wid >> 2) * 64;  // 2 warps along N

    float acc[2][8][4];
    #pragma unroll
    for (int a = 0; a < 2; a++)
        #pragma unroll
        for (int b = 0; b < 8; b++)
            #pragma unroll
            for (int c = 0; c < 4; c++) acc[a][b][c] = 0.0f;

    load_stage(0);
    load_stage(1);

    for (int s = 0; s < NS; s++) {
        cp_wait1();
        __syncthreads();
        const uint32_t base = sb + (s & 1) * STAGE;

        #pragma unroll
        for (int kk = 0; kk < 2; kk++) {            // two k16 steps per stage
            uint32_t a_h[2][4], a_l[2][4];
            #pragma unroll
            for (int mi = 0; mi < 2; mi++) {
                uint32_t ad = base + OFF_AH +
                    (uint32_t)((wm0 + mi * 16 + (lane & 15)) * 80 + (lane >> 4) * 16 + kk * 32);
                ldsm4(a_h[mi], ad);
                ldsm4(a_l[mi], ad + (OFF_AL - OFF_AH));
            }
            uint32_t b_h[4][4], b_l[4][4];
            #pragma unroll
            for (int p = 0; p < 4; p++) {
                uint32_t nb = (uint32_t)((wn0 + p * 16 + (lane >> 4) * 8) * 2);
                uint32_t bd = base + OFF_BH +
                    (((uint32_t)((kk * 16 + (lane & 15)) * 256) + nb) ^ (uint32_t)((lane & 15) << 4));
                ldsm4t(b_h[p], bd);
                ldsm4t(b_l[p], bd + (OFF_BL - OFF_BH));
            }
            #pragma unroll
            for (int mi = 0; mi < 2; mi++)
                #pragma unroll
                for (int ni = 0; ni < 8; ni++) {
                    int p = ni >> 1, hh = (ni & 1) * 2;
                    mma16816(acc[mi][ni], a_h[mi], b_h[p][hh], b_h[p][hh + 1]);
                    mma16816(acc[mi][ni], a_h[mi], b_l[p][hh], b_l[p][hh + 1]);
                    mma16816(acc[mi][ni], a_l[mi], b_h[p][hh], b_h[p][hh + 1]);
                }
        }
        __syncthreads();
        if (s + 2 < NS) load_stage(s + 2);
        else cp_commit();                           // keep group count aligned
    }

    // Epilogue. c-frag: rows (lane>>2) and +8; cols 2*(lane&3), +1 per n8 tile.
    #pragma unroll
    for (int mi = 0; mi < 2; mi++) {
        #pragma unroll
        for (int half = 0; half < 2; half++) {
            int r = wm0 + mi * 16 + (lane >> 2) + half * 8;
            if (r >= mvalid) continue;
            #pragma unroll
            for (int ni = 0; ni < 8; ni++) {
                int cl = wn0 + ni * 8 + (lane & 3) * 2;
                float v0 = acc[mi][ni][half * 2]     + sBias[cl];
                float v1 = acc[mi][ni][half * 2 + 1] + sBias[cl + 1];
                if (MODE == 0) {
                    v0 = fmaxf(v0, 0.0f);
                    v1 = fmaxf(v1, 0.0f);
                    __nv_bfloat16 h0 = __float2bfloat16(v0);
                    __nv_bfloat16 h1 = __float2bfloat16(v1);
                    __nv_bfloat16 l0 = __float2bfloat16(v0 - __bfloat162float(h0));
                    __nv_bfloat16 l1 = __float2bfloat16(v1 - __bfloat162float(h1));
                    size_t p = (size_t)(arow0 + r) * NTOT + n0 + cl;
                    *(__nv_bfloat162*)(oh + p) = __nv_bfloat162(h0, h1);
                    *(__nv_bfloat162*)(ol + p) = __nv_bfloat162(l0, l1);
                } else {
                    size_t p = (size_t)sPerm[r] * NTOT + n0 + cl;
                    *(float2*)(outf + p) = make_float2(v0, v1);
                }
            }
        }
    }
}

// ---------------------------------------------------------------------------
extern "C" void kernel_launch(void* const* d_in, const int* in_sizes, int n_in,
                              void* d_out, int out_size) {
    const float* z  = (const float*)d_in[0];   // [B, Z]
    const float* W1 = (const float*)d_in[1];   // [E, Z, H]
    const float* b1 = (const float*)d_in[2];   // [E, H]
    const float* W2 = (const float*)d_in[3];   // [E, H, O]
    const float* b2 = (const float*)d_in[4];   // [E, O]
    float* out = (float*)d_out;                // [B, O]

    cudaFuncSetAttribute(moe_mma<0>, cudaFuncAttributeMaxDynamicSharedMemorySize, SMEM_TOTAL);
    cudaFuncSetAttribute(moe_mma<1>, cudaFuncAttributeMaxDynamicSharedMemorySize, SMEM_TOTAL);

    __nv_bfloat16 *zg_h, *zg_l, *hg_h, *hg_l, *w1h, *w1l, *w2h, *w2l;
    cudaGetSymbolAddress((void**)&zg_h, g_zg_h);
    cudaGetSymbolAddress((void**)&zg_l, g_zg_l);
    cudaGetSymbolAddress((void**)&hg_h, g_hg_h);
    cudaGetSymbolAddress((void**)&hg_l, g_hg_l);
    cudaGetSymbolAddress((void**)&w1h, g_w1_h);
    cudaGetSymbolAddress((void**)&w1l, g_w1_l);
    cudaGetSymbolAddress((void**)&w2h, g_w2_h);
    cudaGetSymbolAddress((void**)&w2l, g_w2_l);

    zero_kernel<<<1, 32>>>();
    route_kernel<<<B_ / 256, 256>>>(z);
    scan_kernel<<<1, 1>>>();
    scatter_kernel<<<B_ / 256, 256>>>();
    gather_split_z<<<(B_ * Z_) / 256, 256>>>(z);

    {   // W1 split
        int n4 = E_ * Z_ * H_ / 4;
        split_w<<<(n4 + 255) / 256, 256>>>((const float4*)W1,
                                           (__nv_bfloat162*)w1h, (__nv_bfloat162*)w1l, n4);
    }
    {   // W2 split
        int n4 = (int)((size_t)E_ * H_ * O_ / 4);
        split_w<<<(n4 + 255) / 256, 256>>>((const float4*)W2,
                                           (__nv_bfloat162*)w2h, (__nv_bfloat162*)w2l, n4);
    }

    // Layer 1: h = relu(z @ W1 + b1); K=128, N=1024
    {
        dim3 grid(H_ / BN, MAXT);
        moe_mma<0><<<grid, 256, SMEM_TOTAL>>>(zg_h, zg_l, w1h, w1l, b1,
                                              hg_h, hg_l, nullptr, Z_, H_);
    }
    // Layer 2: y = h @ W2 + b2; K=1024, N=3072, scatter fp32
    {
        dim3 grid(O_ / BN, MAXT);
        moe_mma<1><<<grid, 256, SMEM_TOTAL>>>(hg_h, hg_l, w2h, w2l, b2,
                                              nullptr, nullptr, out, H_, O_);
    }
}

// round 6
// speedup vs baseline: 2.4831x; 1.1049x over previous
#include <cuda_runtime.h>
#include <cuda_bf16.h>
#include <cstdint>

// ---------------------------------------------------------------------------
constexpr int B_ = 2048, Z_ = 128, H_ = 1024, O_ = 3072, E_ = 8;
constexpr int MAXT = B_ / 128 + E_;   // 24
constexpr int BM = 128, BN = 128, BK = 32;
constexpr int NSTG = 3;

// SMEM layout (per stage): A hi/lo 128x32 bf16 (80B-stride rows), B hi/lo 32x128
constexpr int OFF_AH = 0;
constexpr int OFF_AL = 10240;
constexpr int OFF_BH = 20480;
constexpr int OFF_BL = 28672;
constexpr int STAGE  = 36864;
constexpr int OFF_BIAS = NSTG * STAGE;       // 110592 (128 floats)
constexpr int OFF_PERM = OFF_BIAS + 512;
constexpr int SMEM_TOTAL = OFF_PERM + 512;   // 111616

// ---------------------------------------------------------------------------
__device__ int g_idx[B_], g_counts[E_], g_offsets[E_ + 1], g_cursor[E_], g_perm[B_];
__device__ int g_tile_e[MAXT], g_tile_r[MAXT], g_num_tiles;

__device__ __align__(16) __nv_bfloat16 g_zg_h[(B_ + 128) * Z_];
__device__ __align__(16) __nv_bfloat16 g_zg_l[(B_ + 128) * Z_];
__device__ __align__(16) __nv_bfloat16 g_hg_h[(B_ + 128) * H_];
__device__ __align__(16) __nv_bfloat16 g_hg_l[(B_ + 128) * H_];
__device__ __align__(16) __nv_bfloat16 g_w1_h[E_ * Z_ * H_];
__device__ __align__(16) __nv_bfloat16 g_w1_l[E_ * Z_ * H_];
__device__ __align__(16) __nv_bfloat16 g_w2_h[(size_t)E_ * H_ * O_];
__device__ __align__(16) __nv_bfloat16 g_w2_l[(size_t)E_ * H_ * O_];

// ---------------------------------------------------------------------------
// PTX helpers (arch-agnostic, sm_80+)
// ---------------------------------------------------------------------------
__device__ __forceinline__ uint32_t smem_u32(const void* p) {
    return (uint32_t)__cvta_generic_to_shared(p);
}
__device__ __forceinline__ void cp16(uint32_t dst, const void* src) {
    asm volatile("cp.async.cg.shared.global [%0], [%1], 16;" :: "r"(dst), "l"(src) : "memory");
}
__device__ __forceinline__ void cp_commit() {
    asm volatile("cp.async.commit_group;" ::: "memory");
}
__device__ __forceinline__ void cp_wait2() {
    asm volatile("cp.async.wait_group 2;" ::: "memory");
}
__device__ __forceinline__ void ldsm4(uint32_t* r, uint32_t a) {
    asm volatile("ldmatrix.sync.aligned.m8n8.x4.shared.b16 {%0,%1,%2,%3}, [%4];"
                 : "=r"(r[0]), "=r"(r[1]), "=r"(r[2]), "=r"(r[3]) : "r"(a));
}
__device__ __forceinline__ void ldsm4t(uint32_t* r, uint32_t a) {
    asm volatile("ldmatrix.sync.aligned.m8n8.x4.trans.shared.b16 {%0,%1,%2,%3}, [%4];"
                 : "=r"(r[0]), "=r"(r[1]), "=r"(r[2]), "=r"(r[3]) : "r"(a));
}
__device__ __forceinline__ void mma16816(float* d, const uint32_t* a, uint32_t b0, uint32_t b1) {
    asm volatile(
        "mma.sync.aligned.m16n8k16.row.col.f32.bf16.bf16.f32 "
        "{%0,%1,%2,%3}, {%4,%5,%6,%7}, {%8,%9}, {%0,%1,%2,%3};"
        : "+f"(d[0]), "+f"(d[1]), "+f"(d[2]), "+f"(d[3])
        : "r"(a[0]), "r"(a[1]), "r"(a[2]), "r"(a[3]), "r"(b0), "r"(b1));
}

// ---------------------------------------------------------------------------
// Routing (bit-exact vs JAX: exact small integers in fp32, order-independent)
// ---------------------------------------------------------------------------
__global__ void zero_kernel() {
    int t = threadIdx.x;
    if (t < E_) { g_counts[t] = 0; g_cursor[t] = 0; }
}
__global__ void route_kernel(const float* __restrict__ z) {
    int i = blockIdx.x * blockDim.x + threadIdx.x;
    if (i >= B_) return;
    const float* zr = z + (size_t)i * Z_;
    float s = 0.0f;
    #pragma unroll 8
    for (int k = 0; k < Z_; k++)
        s += floorf(fabsf(zr[k]) * 1000.0f);
    int e = ((int)s) & (E_ - 1);
    g_idx[i] = e;
    atomicAdd(&g_counts[e], 1);
}
__global__ void scan_kernel() {
    int o = 0, nt = 0;
    g_offsets[0] = 0;
    for (int e = 0; e < E_; e++) {
        int c = g_counts[e];
        for (int r = 0; r < c; r += BM) { g_tile_e[nt] = e; g_tile_r[nt] = r; nt++; }
        o += c;
        g_offsets[e + 1] = o;
    }
    g_num_tiles = nt;
}
__global__ void scatter_kernel() {
    int i = blockIdx.x * blockDim.x + threadIdx.x;
    if (i >= B_) return;
    int e = g_idx[i];
    int pos = g_offsets[e] + atomicAdd(&g_cursor[e], 1);
    g_perm[pos] = i;
}

// ---------------------------------------------------------------------------
// Conversions
// ---------------------------------------------------------------------------
__global__ void gather_split_z(const float* __restrict__ z) {
    int idx = blockIdx.x * blockDim.x + threadIdx.x;
    if (idx >= B_ * Z_) return;
    int p = idx >> 7;
    int k = idx & (Z_ - 1);
    float v = z[(size_t)g_perm[p] * Z_ + k];
    __nv_bfloat16 h = __float2bfloat16(v);
    g_zg_h[idx] = h;
    g_zg_l[idx] = __float2bfloat16(v - __bfloat162float(h));
}

__global__ void split_w(const float4* __restrict__ src,
                        __nv_bfloat162* __restrict__ dh,
                        __nv_bfloat162* __restrict__ dl, int n4) {
    int i = blockIdx.x * blockDim.x + threadIdx.x;
    if (i >= n4) return;
    float4 v = src[i];
    __nv_bfloat16 h0 = __float2bfloat16(v.x), h1 = __float2bfloat16(v.y);
    __nv_bfloat16 h2 = __float2bfloat16(v.z), h3 = __float2bfloat16(v.w);
    __nv_bfloat16 l0 = __float2bfloat16(v.x - __bfloat162float(h0));
    __nv_bfloat16 l1 = __float2bfloat16(v.y - __bfloat162float(h1));
    __nv_bfloat16 l2 = __float2bfloat16(v.z - __bfloat162float(h2));
    __nv_bfloat16 l3 = __float2bfloat16(v.w - __bfloat162float(h3));
    dh[2 * i]     = __nv_bfloat162(h0, h1);
    dh[2 * i + 1] = __nv_bfloat162(h2, h3);
    dl[2 * i]     = __nv_bfloat162(l0, l1);
    dl[2 * i + 1] = __nv_bfloat162(l2, l3);
}

// ---------------------------------------------------------------------------
// mma.sync grouped GEMM, 3-stage cp.async pipeline, 2 CTAs/SM.
// C[128x128] tile = A[128xK] (perm rows) * B[K x NTOT], 3-term bf16 split.
// MODE 0: relu(x+bias) -> bf16 hi/lo stores (perm-order rows)
// MODE 1: x+bias -> fp32 scatter to original rows via perm
// ---------------------------------------------------------------------------
template <int MODE>
__global__ __launch_bounds__(256, 2)
void moe_mma(const __nv_bfloat16* __restrict__ Ah, const __nv_bfloat16* __restrict__ Al,
             const __nv_bfloat16* __restrict__ Bh, const __nv_bfloat16* __restrict__ Bl,
             const float* __restrict__ bias,
             __nv_bfloat16* __restrict__ oh, __nv_bfloat16* __restrict__ ol,
             float* __restrict__ outf, int K, int NTOT) {
    const int tile = blockIdx.y;
    if (tile >= g_num_tiles) return;
    const int e      = g_tile_e[tile];
    const int row0   = g_tile_r[tile];
    const int off    = g_offsets[e];
    const int cnt    = g_offsets[e + 1] - off;
    const int mvalid = min(BM, cnt - row0);
    const int n0     = blockIdx.x * BN;
    const int arow0  = off + row0;

    extern __shared__ char smem[];
    const uint32_t sb = smem_u32(smem);
    float* sBias = (float*)(smem + OFF_BIAS);
    int*   sPerm = (int*)(smem + OFF_PERM);

    const int t = threadIdx.x;
    const int lane = t & 31;
    const int wid = t >> 5;

    if (t < 128) {
        sBias[t] = bias[(size_t)e * NTOT + n0 + t];
        if (MODE == 1) sPerm[t] = (t < mvalid) ? g_perm[arow0 + t] : 0;
    }

    const __nv_bfloat16* BhE = Bh + (size_t)e * NTOT * K;
    const __nv_bfloat16* BlE = Bl + (size_t)e * NTOT * K;
    const int NS = K / BK;

    auto load_stage = [&](int s) {
        const int k0 = s * BK;
        const uint32_t base = sb + (s % NSTG) * STAGE;
        #pragma unroll
        for (int i = 0; i < 2; i++) {               // A: 512 chunks of 16B (hi+lo)
            int idx = t + i * 256;
            int r = idx >> 2, kc = idx & 3;
            uint32_t d = (uint32_t)(r * 80 + kc * 16);
            size_t so = (size_t)(arow0 + r) * K + k0 + kc * 8;
            cp16(base + OFF_AH + d, Ah + so);
            cp16(base + OFF_AL + d, Al + so);
        }
        #pragma unroll
        for (int i = 0; i < 2; i++) {               // B: 512 chunks of 16B (hi+lo)
            int idx = t + i * 256;
            int kr = idx >> 4, nc = idx & 15;
            uint32_t d = (uint32_t)(kr * 256 + nc * 16) ^ (uint32_t)((kr & 15) << 4);
            size_t so = (size_t)(k0 + kr) * NTOT + n0 + nc * 8;
            cp16(base + OFF_BH + d, BhE + so);
            cp16(base + OFF_BL + d, BlE + so);
        }
        cp_commit();
    };

    const int wm0 = (wid & 3) * 32;   // 4 warps along M
    const int wn0 = (wid >> 2) * 64;  // 2 warps along N

    float acc[2][8][4];
    #pragma unroll
    for (int a = 0; a < 2; a++)
        #pragma unroll
        for (int b = 0; b < 8; b++)
            #pragma unroll
            for (int c = 0; c < 4; c++) acc[a][b][c] = 0.0f;

    load_stage(0);
    load_stage(1);
    load_stage(2);

    for (int s = 0; s < NS; s++) {
        cp_wait2();
        __syncthreads();
        const uint32_t base = sb + (s % NSTG) * STAGE;

        #pragma unroll
        for (int kk = 0; kk < 2; kk++) {            // two k16 steps per stage
            uint32_t a_h[2][4], a_l[2][4];
            #pragma unroll
            for (int mi = 0; mi < 2; mi++) {
                uint32_t ad = base + OFF_AH +
                    (uint32_t)((wm0 + mi * 16 + (lane & 15)) * 80 + (lane >> 4) * 16 + kk * 32);
                ldsm4(a_h[mi], ad);
                ldsm4(a_l[mi], ad + (OFF_AL - OFF_AH));
            }
            // process n-tiles in two halves to cap live b registers
            #pragma unroll
            for (int pp = 0; pp < 2; pp++) {
                uint32_t b_h[2][4], b_l[2][4];
                #pragma unroll
                for (int q = 0; q < 2; q++) {
                    int p = pp * 2 + q;
                    uint32_t nb = (uint32_t)((wn0 + p * 16 + (lane >> 4) * 8) * 2);
                    uint32_t bd = base + OFF_BH +
                        (((uint32_t)((kk * 16 + (lane & 15)) * 256) + nb) ^ (uint32_t)((lane & 15) << 4));
                    ldsm4t(b_h[q], bd);
                    ldsm4t(b_l[q], bd + (OFF_BL - OFF_BH));
                }
                #pragma unroll
                for (int mi = 0; mi < 2; mi++)
                    #pragma unroll
                    for (int nq = 0; nq < 4; nq++) {
                        int ni = pp * 4 + nq;
                        int q = nq >> 1, hh = (nq & 1) * 2;
                        mma16816(acc[mi][ni], a_h[mi], b_h[q][hh], b_h[q][hh + 1]);
                        mma16816(acc[mi][ni], a_h[mi], b_l[q][hh], b_l[q][hh + 1]);
                        mma16816(acc[mi][ni], a_l[mi], b_h[q][hh], b_h[q][hh + 1]);
                    }
            }
        }
        __syncthreads();
        if (s + 3 < NS) load_stage(s + 3);
        else cp_commit();                           // keep group count aligned
    }

    // Epilogue. c-frag: rows (lane>>2) and +8; cols 2*(lane&3), +1 per n8 tile.
    #pragma unroll
    for (int mi = 0; mi < 2; mi++) {
        #pragma unroll
        for (int half = 0; half < 2; half++) {
            int r = wm0 + mi * 16 + (lane >> 2) + half * 8;
            if (r >= mvalid) continue;
            #pragma unroll
            for (int ni = 0; ni < 8; ni++) {
                int cl = wn0 + ni * 8 + (lane & 3) * 2;
                float v0 = acc[mi][ni][half * 2]     + sBias[cl];
                float v1 = acc[mi][ni][half * 2 + 1] + sBias[cl + 1];
                if (MODE == 0) {
                    v0 = fmaxf(v0, 0.0f);
                    v1 = fmaxf(v1, 0.0f);
                    __nv_bfloat16 h0 = __float2bfloat16(v0);
                    __nv_bfloat16 h1 = __float2bfloat16(v1);
                    __nv_bfloat16 l0 = __float2bfloat16(v0 - __bfloat162float(h0));
                    __nv_bfloat16 l1 = __float2bfloat16(v1 - __bfloat162float(h1));
                    size_t p = (size_t)(arow0 + r) * NTOT + n0 + cl;
                    *(__nv_bfloat162*)(oh + p) = __nv_bfloat162(h0, h1);
                    *(__nv_bfloat162*)(ol + p) = __nv_bfloat162(l0, l1);
                } else {
                    size_t p = (size_t)sPerm[r] * NTOT + n0 + cl;
                    *(float2*)(outf + p) = make_float2(v0, v1);
                }
            }
        }
    }
}

// ---------------------------------------------------------------------------
extern "C" void kernel_launch(void* const* d_in, const int* in_sizes, int n_in,
                              void* d_out, int out_size) {
    const float* z  = (const float*)d_in[0];
    const float* W1 = (const float*)d_in[1];
    const float* b1 = (const float*)d_in[2];
    const float* W2 = (const float*)d_in[3];
    const float* b2 = (const float*)d_in[4];
    float* out = (float*)d_out;

    cudaFuncSetAttribute(moe_mma<0>, cudaFuncAttributeMaxDynamicSharedMemorySize, SMEM_TOTAL);
    cudaFuncSetAttribute(moe_mma<1>, cudaFuncAttributeMaxDynamicSharedMemorySize, SMEM_TOTAL);

    __nv_bfloat16 *zg_h, *zg_l, *hg_h, *hg_l, *w1h, *w1l, *w2h, *w2l;
    cudaGetSymbolAddress((void**)&zg_h, g_zg_h);
    cudaGetSymbolAddress((void**)&zg_l, g_zg_l);
    cudaGetSymbolAddress((void**)&hg_h, g_hg_h);
    cudaGetSymbolAddress((void**)&hg_l, g_hg_l);
    cudaGetSymbolAddress((void**)&w1h, g_w1_h);
    cudaGetSymbolAddress((void**)&w1l, g_w1_l);
    cudaGetSymbolAddress((void**)&w2h, g_w2_h);
    cudaGetSymbolAddress((void**)&w2l, g_w2_l);

    zero_kernel<<<1, 32>>>();
    route_kernel<<<B_ / 256, 256>>>(z);
    scan_kernel<<<1, 1>>>();
    scatter_kernel<<<B_ / 256, 256>>>();
    gather_split_z<<<(B_ * Z_) / 256, 256>>>(z);

    {   // W1 split
        int n4 = E_ * Z_ * H_ / 4;
        split_w<<<(n4 + 255) / 256, 256>>>((const float4*)W1,
                                           (__nv_bfloat162*)w1h, (__nv_bfloat162*)w1l, n4);
    }
    {   // W2 split
        int n4 = (int)((size_t)E_ * H_ * O_ / 4);
        split_w<<<(n4 + 255) / 256, 256>>>((const float4*)W2,
                                           (__nv_bfloat162*)w2h, (__nv_bfloat162*)w2l, n4);
    }

    // Layer 1: h = relu(z @ W1 + b1); K=128, N=1024
    {
        dim3 grid(H_ / BN, MAXT);
        moe_mma<0><<<grid, 256, SMEM_TOTAL>>>(zg_h, zg_l, w1h, w1l, b1,
                                              hg_h, hg_l, nullptr, Z_, H_);
    }
    // Layer 2: y = h @ W2 + b2; K=1024, N=3072, scatter fp32
    {
        dim3 grid(O_ / BN, MAXT);
        moe_mma<1><<<grid, 256, SMEM_TOTAL>>>(hg_h, hg_l, w2h, w2l, b2,
                                              nullptr, nullptr, out, H_, O_);
    }
}

// round 7
// speedup vs baseline: 2.5457x; 1.0252x over previous
#include <cuda_runtime.h>
#include <cuda_bf16.h>
#include <cstdint>

// ---------------------------------------------------------------------------
constexpr int B_ = 2048, Z_ = 128, H_ = 1024, O_ = 3072, E_ = 8;
constexpr int MAXT = B_ / 128 + E_;   // 24
constexpr int BM = 128, BN = 128, BK = 32;
constexpr int NSTG = 3;

// SMEM layout (per stage): A hi/lo 128x32 bf16 (80B-stride rows), B hi/lo 32x128
constexpr int OFF_AH = 0;
constexpr int OFF_AL = 10240;
constexpr int OFF_BH = 20480;
constexpr int OFF_BL = 28672;
constexpr int STAGE  = 36864;
constexpr int OFF_BIAS = NSTG * STAGE;       // 110592 (128 floats)
constexpr int OFF_PERM = OFF_BIAS + 512;
constexpr int SMEM_TOTAL = OFF_PERM + 512;   // 111616

constexpr int G1_BLOCKS = (H_ / BN) * MAXT;  // 192 gemm1 blocks in fusedB
constexpr int SPLITB    = 2048;              // split-W2 blocks in fusedB

// ---------------------------------------------------------------------------
__device__ int g_idx[B_], g_offsets[E_ + 1], g_perm[B_];
__device__ int g_tile_e[MAXT], g_tile_r[MAXT], g_num_tiles;

__device__ __align__(16) __nv_bfloat16 g_zg_h[(B_ + 128) * Z_];
__device__ __align__(16) __nv_bfloat16 g_zg_l[(B_ + 128) * Z_];
__device__ __align__(16) __nv_bfloat16 g_hg_h[(B_ + 128) * H_];
__device__ __align__(16) __nv_bfloat16 g_hg_l[(B_ + 128) * H_];
__device__ __align__(16) __nv_bfloat16 g_w1_h[E_ * Z_ * H_];
__device__ __align__(16) __nv_bfloat16 g_w1_l[E_ * Z_ * H_];
__device__ __align__(16) __nv_bfloat16 g_w2_h[(size_t)E_ * H_ * O_];
__device__ __align__(16) __nv_bfloat16 g_w2_l[(size_t)E_ * H_ * O_];

// ---------------------------------------------------------------------------
// PTX helpers (arch-agnostic, sm_80+)
// ---------------------------------------------------------------------------
__device__ __forceinline__ uint32_t smem_u32(const void* p) {
    return (uint32_t)__cvta_generic_to_shared(p);
}
__device__ __forceinline__ void cp16(uint32_t dst, const void* src) {
    asm volatile("cp.async.cg.shared.global [%0], [%1], 16;" :: "r"(dst), "l"(src) : "memory");
}
__device__ __forceinline__ void cp_commit() {
    asm volatile("cp.async.commit_group;" ::: "memory");
}
__device__ __forceinline__ void cp_wait2() {
    asm volatile("cp.async.wait_group 2;" ::: "memory");
}
__device__ __forceinline__ void ldsm4(uint32_t* r, uint32_t a) {
    asm volatile("ldmatrix.sync.aligned.m8n8.x4.shared.b16 {%0,%1,%2,%3}, [%4];"
                 : "=r"(r[0]), "=r"(r[1]), "=r"(r[2]), "=r"(r[3]) : "r"(a));
}
__device__ __forceinline__ void ldsm4t(uint32_t* r, uint32_t a) {
    asm volatile("ldmatrix.sync.aligned.m8n8.x4.trans.shared.b16 {%0,%1,%2,%3}, [%4];"
                 : "=r"(r[0]), "=r"(r[1]), "=r"(r[2]), "=r"(r[3]) : "r"(a));
}
__device__ __forceinline__ void mma16816(float* d, const uint32_t* a, uint32_t b0, uint32_t b1) {
    asm volatile(
        "mma.sync.aligned.m16n8k16.row.col.f32.bf16.bf16.f32 "
        "{%0,%1,%2,%3}, {%4,%5,%6,%7}, {%8,%9}, {%0,%1,%2,%3};"
        : "+f"(d[0]), "+f"(d[1]), "+f"(d[2]), "+f"(d[3])
        : "r"(a[0]), "r"(a[1]), "r"(a[2]), "r"(a[3]), "r"(b0), "r"(b1));
}

__device__ __forceinline__ void split4(float4 v, __nv_bfloat162* dh,
                                       __nv_bfloat162* dl, int i) {
    __nv_bfloat16 h0 = __float2bfloat16(v.x), h1 = __float2bfloat16(v.y);
    __nv_bfloat16 h2 = __float2bfloat16(v.z), h3 = __float2bfloat16(v.w);
    __nv_bfloat16 l0 = __float2bfloat16(v.x - __bfloat162float(h0));
    __nv_bfloat16 l1 = __float2bfloat16(v.y - __bfloat162float(h1));
    __nv_bfloat16 l2 = __float2bfloat16(v.z - __bfloat162float(h2));
    __nv_bfloat16 l3 = __float2bfloat16(v.w - __bfloat162float(h3));
    dh[2 * i]     = __nv_bfloat162(h0, h1);
    dh[2 * i + 1] = __nv_bfloat162(h2, h3);
    dl[2 * i]     = __nv_bfloat162(l0, l1);
    dl[2 * i + 1] = __nv_bfloat162(l2, l3);
}

// ---------------------------------------------------------------------------
// Routing (bit-exact vs JAX: exact small integers in fp32, order-independent)
// ---------------------------------------------------------------------------
__global__ void route_kernel(const float* __restrict__ z) {
    int i = blockIdx.x * blockDim.x + threadIdx.x;
    if (i >= B_) return;
    const float* zr = z + (size_t)i * Z_;
    float s = 0.0f;
    #pragma unroll 8
    for (int k = 0; k < Z_; k++)
        s += floorf(fabsf(zr[k]) * 1000.0f);
    g_idx[i] = ((int)s) & (E_ - 1);
}

// One block: histogram -> offsets + tile list -> perm scatter.
__global__ void scan_scatter() {
    __shared__ int cnt[E_], cur[E_], offs[E_];
    int t = threadIdx.x;
    if (t < E_) { cnt[t] = 0; cur[t] = 0; }
    __syncthreads();
    for (int i = t; i < B_; i += blockDim.x) atomicAdd(&cnt[g_idx[i]], 1);
    __syncthreads();
    if (t == 0) {
        int o = 0, nt = 0;
        g_offsets[0] = 0;
        for (int e = 0; e < E_; e++) {
            int c = cnt[e];
            offs[e] = o;
            for (int r = 0; r < c; r += BM) { g_tile_e[nt] = e; g_tile_r[nt] = r; nt++; }
            o += c;
            g_offsets[e + 1] = o;
        }
        g_num_tiles = nt;
    }
    __syncthreads();
    for (int i = t; i < B_; i += blockDim.x) {
        int e = g_idx[i];
        int pos = offs[e] + atomicAdd(&cur[e], 1);
        g_perm[pos] = i;
    }
}

// Fused: gather+split z (blocks 0..255) and split W1 (blocks 256..1279)
__global__ void prep_a(const float4* __restrict__ z4, const float4* __restrict__ W1) {
    int bid = blockIdx.x, t = threadIdx.x;
    if (bid < 256) {
        int idx = bid * 256 + t;            // float4 index, row-gathered z
        int p = idx >> 5, k4 = idx & 31;    // 32 float4 per row
        float4 v = z4[(size_t)g_perm[p] * 32 + k4];
        split4(v, (__nv_bfloat162*)g_zg_h, (__nv_bfloat162*)g_zg_l, idx);
    } else {
        int i = (bid - 256) * 256 + t;      // < 262144
        split4(W1[i], (__nv_bfloat162*)g_w1_h, (__nv_bfloat162*)g_w1_l, i);
    }
}

// ---------------------------------------------------------------------------
// Grouped GEMM tile (mma.sync, 3-stage cp.async pipeline), as device function.
// MODE 0: relu(x+bias) -> bf16 hi/lo stores (perm-order rows)
// MODE 1: x+bias -> fp32 scatter to original rows via perm
// ---------------------------------------------------------------------------
template <int MODE>
__device__ void moe_gemm_tile(
    const __nv_bfloat16* __restrict__ Ah, const __nv_bfloat16* __restrict__ Al,
    const __nv_bfloat16* __restrict__ Bh, const __nv_bfloat16* __restrict__ Bl,
    const float* __restrict__ bias,
    __nv_bfloat16* __restrict__ oh, __nv_bfloat16* __restrict__ ol,
    float* __restrict__ outf, int K, int NTOT, int nblk, int tile, char* smem) {

    const int e      = g_tile_e[tile];
    const int row0   = g_tile_r[tile];
    const int off    = g_offsets[e];
    const int cnt    = g_offsets[e + 1] - off;
    const int mvalid = min(BM, cnt - row0);
    const int n0     = nblk * BN;
    const int arow0  = off + row0;

    const uint32_t sb = smem_u32(smem);
    float* sBias = (float*)(smem + OFF_BIAS);
    int*   sPerm = (int*)(smem + OFF_PERM);

    const int t = threadIdx.x;
    const int lane = t & 31;
    const int wid = t >> 5;

    if (t < 128) {
        sBias[t] = bias[(size_t)e * NTOT + n0 + t];
        if (MODE == 1) sPerm[t] = (t < mvalid) ? g_perm[arow0 + t] : 0;
    }

    const __nv_bfloat16* BhE = Bh + (size_t)e * NTOT * K;
    const __nv_bfloat16* BlE = Bl + (size_t)e * NTOT * K;
    const int NS = K / BK;

    auto load_stage = [&](int s) {
        const int k0 = s * BK;
        const uint32_t base = sb + (s % NSTG) * STAGE;
        #pragma unroll
        for (int i = 0; i < 2; i++) {               // A: 512 chunks of 16B (hi+lo)
            int idx = t + i * 256;
            int r = idx >> 2, kc = idx & 3;
            uint32_t d = (uint32_t)(r * 80 + kc * 16);
            size_t so = (size_t)(arow0 + r) * K + k0 + kc * 8;
            cp16(base + OFF_AH + d, Ah + so);
            cp16(base + OFF_AL + d, Al + so);
        }
        #pragma unroll
        for (int i = 0; i < 2; i++) {               // B: 512 chunks of 16B (hi+lo)
            int idx = t + i * 256;
            int kr = idx >> 4, nc = idx & 15;
            uint32_t d = (uint32_t)(kr * 256 + nc * 16) ^ (uint32_t)((kr & 15) << 4);
            size_t so = (size_t)(k0 + kr) * NTOT + n0 + nc * 8;
            cp16(base + OFF_BH + d, BhE + so);
            cp16(base + OFF_BL + d, BlE + so);
        }
        cp_commit();
    };

    const int wm0 = (wid & 3) * 32;   // 4 warps along M
    const int wn0 = (wid >> 2) * 64;  // 2 warps along N

    float acc[2][8][4];
    #pragma unroll
    for (int a = 0; a < 2; a++)
        #pragma unroll
        for (int b = 0; b < 8; b++)
            #pragma unroll
            for (int c = 0; c < 4; c++) acc[a][b][c] = 0.0f;

    load_stage(0);
    load_stage(1);
    load_stage(2);

    for (int s = 0; s < NS; s++) {
        cp_wait2();
        __syncthreads();
        const uint32_t base = sb + (s % NSTG) * STAGE;

        #pragma unroll
        for (int kk = 0; kk < 2; kk++) {            // two k16 steps per stage
            uint32_t a_h[2][4], a_l[2][4];
            #pragma unroll
            for (int mi = 0; mi < 2; mi++) {
                uint32_t ad = base + OFF_AH +
                    (uint32_t)((wm0 + mi * 16 + (lane & 15)) * 80 + (lane >> 4) * 16 + kk * 32);
                ldsm4(a_h[mi], ad);
                ldsm4(a_l[mi], ad + (OFF_AL - OFF_AH));
            }
            #pragma unroll
            for (int pp = 0; pp < 2; pp++) {        // two n-halves cap live b-regs
                uint32_t b_h[2][4], b_l[2][4];
                #pragma unroll
                for (int q = 0; q < 2; q++) {
                    int p = pp * 2 + q;
                    uint32_t nb = (uint32_t)((wn0 + p * 16 + (lane >> 4) * 8) * 2);
                    uint32_t bd = base + OFF_BH +
                        (((uint32_t)((kk * 16 + (lane & 15)) * 256) + nb) ^ (uint32_t)((lane & 15) << 4));
                    ldsm4t(b_h[q], bd);
                    ldsm4t(b_l[q], bd + (OFF_BL - OFF_BH));
                }
                #pragma unroll
                for (int mi = 0; mi < 2; mi++)
                    #pragma unroll
                    for (int nq = 0; nq < 4; nq++) {
                        int ni = pp * 4 + nq;
                        int q = nq >> 1, hh = (nq & 1) * 2;
                        mma16816(acc[mi][ni], a_h[mi], b_h[q][hh], b_h[q][hh + 1]);
                        mma16816(acc[mi][ni], a_h[mi], b_l[q][hh], b_l[q][hh + 1]);
                        mma16816(acc[mi][ni], a_l[mi], b_h[q][hh], b_h[q][hh + 1]);
                    }
            }
        }
        __syncthreads();
        if (s + 3 < NS) load_stage(s + 3);
        else cp_commit();                           // keep group count aligned
    }

    // Epilogue. c-frag: rows (lane>>2), +8; cols 2*(lane&3), +1 per n8 tile.
    #pragma unroll
    for (int mi = 0; mi < 2; mi++) {
        #pragma unroll
        for (int half = 0; half < 2; half++) {
            int r = wm0 + mi * 16 + (lane >> 2) + half * 8;
            if (r >= mvalid) continue;
            #pragma unroll
            for (int ni = 0; ni < 8; ni++) {
                int cl = wn0 + ni * 8 + (lane & 3) * 2;
                float v0 = acc[mi][ni][half * 2]     + sBias[cl];
                float v1 = acc[mi][ni][half * 2 + 1] + sBias[cl + 1];
                if (MODE == 0) {
                    v0 = fmaxf(v0, 0.0f);
                    v1 = fmaxf(v1, 0.0f);
                    __nv_bfloat16 h0 = __float2bfloat16(v0);
                    __nv_bfloat16 h1 = __float2bfloat16(v1);
                    __nv_bfloat16 l0 = __float2bfloat16(v0 - __bfloat162float(h0));
                    __nv_bfloat16 l1 = __float2bfloat16(v1 - __bfloat162float(h1));
                    size_t p = (size_t)(arow0 + r) * NTOT + n0 + cl;
                    *(__nv_bfloat162*)(oh + p) = __nv_bfloat162(h0, h1);
                    *(__nv_bfloat162*)(ol + p) = __nv_bfloat162(l0, l1);
                } else {
                    size_t p = (size_t)sPerm[r] * NTOT + n0 + cl;
                    *(float2*)(outf + p) = make_float2(v0, v1);
                }
            }
        }
    }
}

// ---------------------------------------------------------------------------
// fusedB: layer-1 GEMM (blocks 0..191) overlapped with W2 split (rest).
// ---------------------------------------------------------------------------
__global__ __launch_bounds__(256, 2)
void fusedB(const float* __restrict__ b1, const float4* __restrict__ W2) {
    extern __shared__ char smem[];
    int bid = blockIdx.x;
    if (bid < G1_BLOCKS) {
        int tile = bid >> 3;                // 8 n-blocks for N=1024
        if (tile >= g_num_tiles) return;
        moe_gemm_tile<0>(g_zg_h, g_zg_l, g_w1_h, g_w1_l, b1,
                         g_hg_h, g_hg_l, nullptr, Z_, H_, bid & 7, tile, smem);
    } else {
        const int n4 = (int)((size_t)E_ * H_ * O_ / 4);
        for (int i = (bid - G1_BLOCKS) * 256 + threadIdx.x; i < n4; i += SPLITB * 256)
            split4(W2[i], (__nv_bfloat162*)g_w2_h, (__nv_bfloat162*)g_w2_l, i);
    }
}

// Layer-2 GEMM
__global__ __launch_bounds__(256, 2)
void moe_mma2(const float* __restrict__ b2, float* __restrict__ out) {
    extern __shared__ char smem[];
    int tile = blockIdx.y;
    if (tile >= g_num_tiles) return;
    moe_gemm_tile<1>(g_hg_h, g_hg_l, g_w2_h, g_w2_l, b2,
                     nullptr, nullptr, out, H_, O_, blockIdx.x, tile, smem);
}

// ---------------------------------------------------------------------------
extern "C" void kernel_launch(void* const* d_in, const int* in_sizes, int n_in,
                              void* d_out, int out_size) {
    const float* z  = (const float*)d_in[0];
    const float* W1 = (const float*)d_in[1];
    const float* b1 = (const float*)d_in[2];
    const float* W2 = (const float*)d_in[3];
    const float* b2 = (const float*)d_in[4];
    float* out = (float*)d_out;

    cudaFuncSetAttribute(fusedB, cudaFuncAttributeMaxDynamicSharedMemorySize, SMEM_TOTAL);
    cudaFuncSetAttribute(moe_mma2, cudaFuncAttributeMaxDynamicSharedMemorySize, SMEM_TOTAL);

    route_kernel<<<B_ / 256, 256>>>(z);
    scan_scatter<<<1, 1024>>>();
    prep_a<<<1280, 256>>>((const float4*)z, (const float4*)W1);
    fusedB<<<G1_BLOCKS + SPLITB, 256, SMEM_TOTAL>>>(b1, (const float4*)W2);
    moe_mma2<<<dim3(O_ / BN, MAXT), 256, SMEM_TOTAL>>>(b2, out);
}

// round 8
// speedup vs baseline: 3.1917x; 1.2538x over previous
#include <cuda_runtime.h>
#include <cuda_bf16.h>
#include <cuda_fp16.h>
#include <cstdint>

// ---------------------------------------------------------------------------
constexpr int B_ = 2048, Z_ = 128, H_ = 1024, O_ = 3072, E_ = 8;
constexpr int MAXT = B_ / 128 + E_;   // 24
constexpr int BM = 128, BN = 128, BK = 32;
constexpr int NSTG = 3;

// GEMM1 (bf16 3-term) stage layout: A hi/lo 128x32 (80B-stride), B hi/lo 32x128
constexpr int OFF_AH = 0;
constexpr int OFF_AL = 10240;
constexpr int OFF_BH = 20480;
constexpr int OFF_BL = 28672;
constexpr int STAGE  = 36864;
constexpr int OFF_BIAS = NSTG * STAGE;       // 110592
constexpr int OFF_PERM = OFF_BIAS + 512;
constexpr int SMEM_TOTAL = OFF_PERM + 512;   // 111616

// GEMM2 (fp16 2-term) stage layout: A hi/lo 128x32 (80B-stride), B single 32x128
constexpr int F2_AH = 0;
constexpr int F2_AL = 10240;
constexpr int F2_B  = 20480;
constexpr int F2_STAGE = 28672;
constexpr int F2_BIAS = NSTG * F2_STAGE;     // 86016
constexpr int F2_PERM = F2_BIAS + 512;
constexpr int SMEM2_TOTAL = F2_PERM + 512;   // 87040

constexpr int G1_BLOCKS = (H_ / BN) * MAXT;  // 192
constexpr int SPLITB    = 2048;

// ---------------------------------------------------------------------------
__device__ int g_idx[B_], g_offsets[E_ + 1], g_perm[B_];
__device__ int g_tile_e[MAXT], g_tile_r[MAXT], g_num_tiles;

__device__ __align__(16) __nv_bfloat16 g_zg_h[(B_ + 128) * Z_];
__device__ __align__(16) __nv_bfloat16 g_zg_l[(B_ + 128) * Z_];
__device__ __align__(16) __half       g_hg_h[(B_ + 128) * H_];
__device__ __align__(16) __half       g_hg_l[(B_ + 128) * H_];
__device__ __align__(16) __nv_bfloat16 g_w1_h[E_ * Z_ * H_];
__device__ __align__(16) __nv_bfloat16 g_w1_l[E_ * Z_ * H_];
__device__ __align__(16) __half       g_w2f[(size_t)E_ * H_ * O_];

// ---------------------------------------------------------------------------
// PTX helpers (arch-agnostic, sm_80+)
// ---------------------------------------------------------------------------
__device__ __forceinline__ uint32_t smem_u32(const void* p) {
    return (uint32_t)__cvta_generic_to_shared(p);
}
__device__ __forceinline__ void cp16(uint32_t dst, const void* src) {
    asm volatile("cp.async.cg.shared.global [%0], [%1], 16;" :: "r"(dst), "l"(src) : "memory");
}
__device__ __forceinline__ void cp_commit() {
    asm volatile("cp.async.commit_group;" ::: "memory");
}
__device__ __forceinline__ void cp_wait2() {
    asm volatile("cp.async.wait_group 2;" ::: "memory");
}
__device__ __forceinline__ void ldsm4(uint32_t* r, uint32_t a) {
    asm volatile("ldmatrix.sync.aligned.m8n8.x4.shared.b16 {%0,%1,%2,%3}, [%4];"
                 : "=r"(r[0]), "=r"(r[1]), "=r"(r[2]), "=r"(r[3]) : "r"(a));
}
__device__ __forceinline__ void ldsm4t(uint32_t* r, uint32_t a) {
    asm volatile("ldmatrix.sync.aligned.m8n8.x4.trans.shared.b16 {%0,%1,%2,%3}, [%4];"
                 : "=r"(r[0]), "=r"(r[1]), "=r"(r[2]), "=r"(r[3]) : "r"(a));
}
__device__ __forceinline__ void mma_bf16(float* d, const uint32_t* a, uint32_t b0, uint32_t b1) {
    asm volatile(
        "mma.sync.aligned.m16n8k16.row.col.f32.bf16.bf16.f32 "
        "{%0,%1,%2,%3}, {%4,%5,%6,%7}, {%8,%9}, {%0,%1,%2,%3};"
        : "+f"(d[0]), "+f"(d[1]), "+f"(d[2]), "+f"(d[3])
        : "r"(a[0]), "r"(a[1]), "r"(a[2]), "r"(a[3]), "r"(b0), "r"(b1));
}
__device__ __forceinline__ void mma_f16(float* d, const uint32_t* a, uint32_t b0, uint32_t b1) {
    asm volatile(
        "mma.sync.aligned.m16n8k16.row.col.f32.f16.f16.f32 "
        "{%0,%1,%2,%3}, {%4,%5,%6,%7}, {%8,%9}, {%0,%1,%2,%3};"
        : "+f"(d[0]), "+f"(d[1]), "+f"(d[2]), "+f"(d[3])
        : "r"(a[0]), "r"(a[1]), "r"(a[2]), "r"(a[3]), "r"(b0), "r"(b1));
}

__device__ __forceinline__ void split4(float4 v, __nv_bfloat162* dh,
                                       __nv_bfloat162* dl, int i) {
    __nv_bfloat16 h0 = __float2bfloat16(v.x), h1 = __float2bfloat16(v.y);
    __nv_bfloat16 h2 = __float2bfloat16(v.z), h3 = __float2bfloat16(v.w);
    __nv_bfloat16 l0 = __float2bfloat16(v.x - __bfloat162float(h0));
    __nv_bfloat16 l1 = __float2bfloat16(v.y - __bfloat162float(h1));
    __nv_bfloat16 l2 = __float2bfloat16(v.z - __bfloat162float(h2));
    __nv_bfloat16 l3 = __float2bfloat16(v.w - __bfloat162float(h3));
    dh[2 * i]     = __nv_bfloat162(h0, h1);
    dh[2 * i + 1] = __nv_bfloat162(h2, h3);
    dl[2 * i]     = __nv_bfloat162(l0, l1);
    dl[2 * i + 1] = __nv_bfloat162(l2, l3);
}

// ---------------------------------------------------------------------------
// Routing (bit-exact vs JAX: exact small integers in fp32, order-independent)
// ---------------------------------------------------------------------------
__global__ void route_kernel(const float* __restrict__ z) {
    int i = blockIdx.x * blockDim.x + threadIdx.x;
    if (i >= B_) return;
    const float* zr = z + (size_t)i * Z_;
    float s = 0.0f;
    #pragma unroll 8
    for (int k = 0; k < Z_; k++)
        s += floorf(fabsf(zr[k]) * 1000.0f);
    g_idx[i] = ((int)s) & (E_ - 1);
}

__global__ void scan_scatter() {
    __shared__ int cnt[E_], cur[E_], offs[E_];
    int t = threadIdx.x;
    if (t < E_) { cnt[t] = 0; cur[t] = 0; }
    __syncthreads();
    for (int i = t; i < B_; i += blockDim.x) atomicAdd(&cnt[g_idx[i]], 1);
    __syncthreads();
    if (t == 0) {
        int o = 0, nt = 0;
        g_offsets[0] = 0;
        for (int e = 0; e < E_; e++) {
            int c = cnt[e];
            offs[e] = o;
            for (int r = 0; r < c; r += BM) { g_tile_e[nt] = e; g_tile_r[nt] = r; nt++; }
            o += c;
            g_offsets[e + 1] = o;
        }
        g_num_tiles = nt;
    }
    __syncthreads();
    for (int i = t; i < B_; i += blockDim.x) {
        int e = g_idx[i];
        int pos = offs[e] + atomicAdd(&cur[e], 1);
        g_perm[pos] = i;
    }
}

// Fused: gather+split z (blocks 0..255) and split W1 (blocks 256..1279)
__global__ void prep_a(const float4* __restrict__ z4, const float4* __restrict__ W1) {
    int bid = blockIdx.x, t = threadIdx.x;
    if (bid < 256) {
        int idx = bid * 256 + t;
        int p = idx >> 5, k4 = idx & 31;
        float4 v = z4[(size_t)g_perm[p] * 32 + k4];
        split4(v, (__nv_bfloat162*)g_zg_h, (__nv_bfloat162*)g_zg_l, idx);
    } else {
        int i = (bid - 256) * 256 + t;
        split4(W1[i], (__nv_bfloat162*)g_w1_h, (__nv_bfloat162*)g_w1_l, i);
    }
}

// ---------------------------------------------------------------------------
// GEMM1 tile: bf16 3-term (z @ W1), relu, fp16 hi/lo output (perm-order rows)
// ---------------------------------------------------------------------------
__device__ void moe_gemm_tile1(const float* __restrict__ bias, int nblk, int tile,
                               char* smem) {
    const int K = Z_, NTOT = H_;
    const int e      = g_tile_e[tile];
    const int row0   = g_tile_r[tile];
    const int off    = g_offsets[e];
    const int cnt    = g_offsets[e + 1] - off;
    const int mvalid = min(BM, cnt - row0);
    const int n0     = nblk * BN;
    const int arow0  = off + row0;

    const uint32_t sb = smem_u32(smem);
    float* sBias = (float*)(smem + OFF_BIAS);
    const int t = threadIdx.x;
    const int lane = t & 31;
    const int wid = t >> 5;

    if (t < 128) sBias[t] = bias[(size_t)e * NTOT + n0 + t];

    const __nv_bfloat16* BhE = g_w1_h + (size_t)e * NTOT * K;
    const __nv_bfloat16* BlE = g_w1_l + (size_t)e * NTOT * K;
    const int NS = K / BK;

    auto load_stage = [&](int s) {
        const int k0 = s * BK;
        const uint32_t base = sb + (s % NSTG) * STAGE;
        #pragma unroll
        for (int i = 0; i < 2; i++) {
            int idx = t + i * 256;
            int r = idx >> 2, kc = idx & 3;
            uint32_t d = (uint32_t)(r * 80 + kc * 16);
            size_t so = (size_t)(arow0 + r) * K + k0 + kc * 8;
            cp16(base + OFF_AH + d, g_zg_h + so);
            cp16(base + OFF_AL + d, g_zg_l + so);
        }
        #pragma unroll
        for (int i = 0; i < 2; i++) {
            int idx = t + i * 256;
            int kr = idx >> 4, nc = idx & 15;
            uint32_t d = (uint32_t)(kr * 256 + nc * 16) ^ (uint32_t)((kr & 15) << 4);
            size_t so = (size_t)(k0 + kr) * NTOT + n0 + nc * 8;
            cp16(base + OFF_BH + d, BhE + so);
            cp16(base + OFF_BL + d, BlE + so);
        }
        cp_commit();
    };

    const int wm0 = (wid & 3) * 32;
    const int wn0 = (wid >> 2) * 64;

    float acc[2][8][4];
    #pragma unroll
    for (int a = 0; a < 2; a++)
        #pragma unroll
        for (int b = 0; b < 8; b++)
            #pragma unroll
            for (int c = 0; c < 4; c++) acc[a][b][c] = 0.0f;

    load_stage(0);
    load_stage(1);
    load_stage(2);

    for (int s = 0; s < NS; s++) {
        cp_wait2();
        __syncthreads();
        const uint32_t base = sb + (s % NSTG) * STAGE;
        #pragma unroll
        for (int kk = 0; kk < 2; kk++) {
            uint32_t a_h[2][4], a_l[2][4];
            #pragma unroll
            for (int mi = 0; mi < 2; mi++) {
                uint32_t ad = base + OFF_AH +
                    (uint32_t)((wm0 + mi * 16 + (lane & 15)) * 80 + (lane >> 4) * 16 + kk * 32);
                ldsm4(a_h[mi], ad);
                ldsm4(a_l[mi], ad + (OFF_AL - OFF_AH));
            }
            #pragma unroll
            for (int pp = 0; pp < 2; pp++) {
                uint32_t b_h[2][4], b_l[2][4];
                #pragma unroll
                for (int q = 0; q < 2; q++) {
                    int p = pp * 2 + q;
                    uint32_t nb = (uint32_t)((wn0 + p * 16 + (lane >> 4) * 8) * 2);
                    uint32_t bd = base + OFF_BH +
                        (((uint32_t)((kk * 16 + (lane & 15)) * 256) + nb) ^ (uint32_t)((lane & 15) << 4));
                    ldsm4t(b_h[q], bd);
                    ldsm4t(b_l[q], bd + (OFF_BL - OFF_BH));
                }
                #pragma unroll
                for (int mi = 0; mi < 2; mi++)
                    #pragma unroll
                    for (int nq = 0; nq < 4; nq++) {
                        int ni = pp * 4 + nq;
                        int q = nq >> 1, hh = (nq & 1) * 2;
                        mma_bf16(acc[mi][ni], a_h[mi], b_h[q][hh], b_h[q][hh + 1]);
                        mma_bf16(acc[mi][ni], a_h[mi], b_l[q][hh], b_l[q][hh + 1]);
                        mma_bf16(acc[mi][ni], a_l[mi], b_h[q][hh], b_h[q][hh + 1]);
                    }
            }
        }
        __syncthreads();
        if (s + 3 < NS) load_stage(s + 3);
        else cp_commit();
    }

    #pragma unroll
    for (int mi = 0; mi < 2; mi++) {
        #pragma unroll
        for (int half = 0; half < 2; half++) {
            int r = wm0 + mi * 16 + (lane >> 2) + half * 8;
            if (r >= mvalid) continue;
            #pragma unroll
            for (int ni = 0; ni < 8; ni++) {
                int cl = wn0 + ni * 8 + (lane & 3) * 2;
                float v0 = fmaxf(acc[mi][ni][half * 2]     + sBias[cl], 0.0f);
                float v1 = fmaxf(acc[mi][ni][half * 2 + 1] + sBias[cl + 1], 0.0f);
                __half h0 = __float2half_rn(v0);
                __half h1 = __float2half_rn(v1);
                __half l0 = __float2half_rn(v0 - __half2float(h0));
                __half l1 = __float2half_rn(v1 - __half2float(h1));
                size_t p = (size_t)(arow0 + r) * NTOT + n0 + cl;
                *(__half2*)(g_hg_h + p) = __halves2half2(h0, h1);
                *(__half2*)(g_hg_l + p) = __halves2half2(l0, l1);
            }
        }
    }
}

// ---------------------------------------------------------------------------
// GEMM2 tile: fp16 2-term (h @ W2), bias, fp32 scatter to original rows
// ---------------------------------------------------------------------------
__device__ void moe_gemm_tile2(const float* __restrict__ bias, float* __restrict__ outf,
                               int nblk, int tile, char* smem) {
    const int K = H_, NTOT = O_;
    const int e      = g_tile_e[tile];
    const int row0   = g_tile_r[tile];
    const int off    = g_offsets[e];
    const int cnt    = g_offsets[e + 1] - off;
    const int mvalid = min(BM, cnt - row0);
    const int n0     = nblk * BN;
    const int arow0  = off + row0;

    const uint32_t sb = smem_u32(smem);
    float* sBias = (float*)(smem + F2_BIAS);
    int*   sPerm = (int*)(smem + F2_PERM);

    const int t = threadIdx.x;
    const int lane = t & 31;
    const int wid = t >> 5;

    if (t < 128) {
        sBias[t] = bias[(size_t)e * NTOT + n0 + t];
        sPerm[t] = (t < mvalid) ? g_perm[arow0 + t] : 0;
    }

    const __half* BE = g_w2f + (size_t)e * NTOT * K;
    const int NS = K / BK;

    auto load_stage = [&](int s) {
        const int k0 = s * BK;
        const uint32_t base = sb + (s % NSTG) * F2_STAGE;
        #pragma unroll
        for (int i = 0; i < 2; i++) {               // A hi/lo: 512 chunks
            int idx = t + i * 256;
            int r = idx >> 2, kc = idx & 3;
            uint32_t d = (uint32_t)(r * 80 + kc * 16);
            size_t so = (size_t)(arow0 + r) * K + k0 + kc * 8;
            cp16(base + F2_AH + d, g_hg_h + so);
            cp16(base + F2_AL + d, g_hg_l + so);
        }
        #pragma unroll
        for (int i = 0; i < 2; i++) {               // B single: 512 chunks
            int idx = t + i * 256;
            int kr = idx >> 4, nc = idx & 15;
            uint32_t d = (uint32_t)(kr * 256 + nc * 16) ^ (uint32_t)((kr & 15) << 4);
            cp16(base + F2_B + d, BE + (size_t)(k0 + kr) * NTOT + n0 + nc * 8);
        }
        cp_commit();
    };

    const int wm0 = (wid & 3) * 32;
    const int wn0 = (wid >> 2) * 64;

    float acc[2][8][4];
    #pragma unroll
    for (int a = 0; a < 2; a++)
        #pragma unroll
        for (int b = 0; b < 8; b++)
            #pragma unroll
            for (int c = 0; c < 4; c++) acc[a][b][c] = 0.0f;

    load_stage(0);
    load_stage(1);
    load_stage(2);

    for (int s = 0; s < NS; s++) {
        cp_wait2();
        __syncthreads();
        const uint32_t base = sb + (s % NSTG) * F2_STAGE;
        #pragma unroll
        for (int kk = 0; kk < 2; kk++) {
            uint32_t a_h[2][4], a_l[2][4];
            #pragma unroll
            for (int mi = 0; mi < 2; mi++) {
                uint32_t ad = base + F2_AH +
                    (uint32_t)((wm0 + mi * 16 + (lane & 15)) * 80 + (lane >> 4) * 16 + kk * 32);
                ldsm4(a_h[mi], ad);
                ldsm4(a_l[mi], ad + (F2_AL - F2_AH));
            }
            uint32_t b[4][4];
            #pragma unroll
            for (int p = 0; p < 4; p++) {
                uint32_t nb = (uint32_t)((wn0 + p * 16 + (lane >> 4) * 8) * 2);
                uint32_t bd = base + F2_B +
                    (((uint32_t)((kk * 16 + (lane & 15)) * 256) + nb) ^ (uint32_t)((lane & 15) << 4));
                ldsm4t(b[p], bd);
            }
            #pragma unroll
            for (int mi = 0; mi < 2; mi++)
                #pragma unroll
                for (int ni = 0; ni < 8; ni++) {
                    int p = ni >> 1, hh = (ni & 1) * 2;
                    mma_f16(acc[mi][ni], a_h[mi], b[p][hh], b[p][hh + 1]);
                    mma_f16(acc[mi][ni], a_l[mi], b[p][hh], b[p][hh + 1]);
                }
        }
        __syncthreads();
        if (s + 3 < NS) load_stage(s + 3);
        else cp_commit();
    }

    #pragma unroll
    for (int mi = 0; mi < 2; mi++) {
        #pragma unroll
        for (int half = 0; half < 2; half++) {
            int r = wm0 + mi * 16 + (lane >> 2) + half * 8;
            if (r >= mvalid) continue;
            #pragma unroll
            for (int ni = 0; ni < 8; ni++) {
                int cl = wn0 + ni * 8 + (lane & 3) * 2;
                float v0 = acc[mi][ni][half * 2]     + sBias[cl];
                float v1 = acc[mi][ni][half * 2 + 1] + sBias[cl + 1];
                size_t p = (size_t)sPerm[r] * NTOT + n0 + cl;
                *(float2*)(outf + p) = make_float2(v0, v1);
            }
        }
    }
}

// ---------------------------------------------------------------------------
// fusedB: layer-1 GEMM (blocks 0..191) overlapped with W2 fp16 convert (rest)
// ---------------------------------------------------------------------------
__global__ __launch_bounds__(256, 2)
void fusedB(const float* __restrict__ b1, const float4* __restrict__ W2) {
    extern __shared__ char smem[];
    int bid = blockIdx.x;
    if (bid < G1_BLOCKS) {
        int tile = bid >> 3;
        if (tile >= g_num_tiles) return;
        moe_gemm_tile1(b1, bid & 7, tile, smem);
    } else {
        const int n4 = (int)((size_t)E_ * H_ * O_ / 4);
        __half2* dst = (__half2*)g_w2f;
        for (int i = (bid - G1_BLOCKS) * 256 + threadIdx.x; i < n4; i += SPLITB * 256) {
            float4 v = W2[i];
            dst[2 * i]     = __halves2half2(__float2half_rn(v.x), __float2half_rn(v.y));
            dst[2 * i + 1] = __halves2half2(__float2half_rn(v.z), __float2half_rn(v.w));
        }
    }
}

__global__ __launch_bounds__(256, 2)
void moe_mma2(const float* __restrict__ b2, float* __restrict__ out) {
    extern __shared__ char smem[];
    int tile = blockIdx.y;
    if (tile >= g_num_tiles) return;
    moe_gemm_tile2(b2, out, blockIdx.x, tile, smem);
}

// ---------------------------------------------------------------------------
extern "C" void kernel_launch(void* const* d_in, const int* in_sizes, int n_in,
                              void* d_out, int out_size) {
    const float* z  = (const float*)d_in[0];
    const float* W1 = (const float*)d_in[1];
    const float* b1 = (const float*)d_in[2];
    const float* W2 = (const float*)d_in[3];
    const float* b2 = (const float*)d_in[4];
    float* out = (float*)d_out;

    cudaFuncSetAttribute(fusedB, cudaFuncAttributeMaxDynamicSharedMemorySize, SMEM_TOTAL);
    cudaFuncSetAttribute(moe_mma2, cudaFuncAttributeMaxDynamicSharedMemorySize, SMEM2_TOTAL);

    route_kernel<<<B_ / 256, 256>>>(z);
    scan_scatter<<<1, 1024>>>();
    prep_a<<<1280, 256>>>((const float4*)z, (const float4*)W1);
    fusedB<<<G1_BLOCKS + SPLITB, 256, SMEM_TOTAL>>>(b1, (const float4*)W2);
    moe_mma2<<<dim3(O_ / BN, MAXT), 256, SMEM2_TOTAL>>>(b2, out);
}

// round 9
// speedup vs baseline: 4.3796x; 1.3722x over previous
#include <cuda_runtime.h>
#include <cuda_bf16.h>
#include <cuda_fp16.h>
#include <cstdint>

// ---------------------------------------------------------------------------
constexpr int B_ = 2048, Z_ = 128, H_ = 1024, O_ = 3072, E_ = 8;
constexpr int MAXT = B_ / 128 + E_;   // 24
constexpr int BM = 128, BN = 128, BK = 32;
constexpr int NSTG = 3;

// GEMM1 (bf16 3-term) stage layout: A hi/lo 128x32 (80B-stride), B hi/lo 32x128
constexpr int OFF_AH = 0;
constexpr int OFF_AL = 10240;
constexpr int OFF_BH = 20480;
constexpr int OFF_BL = 28672;
constexpr int STAGE  = 36864;
constexpr int OFF_BIAS = NSTG * STAGE;       // 110592
constexpr int OFF_PERM = OFF_BIAS + 512;
constexpr int SMEM_TOTAL = OFF_PERM + 512;   // 111616

// GEMM2 (fp16 single-term) stage: A 128x32 fp16 (80B-stride), B 32x128 fp16
constexpr int F2_A  = 0;
constexpr int F2_B  = 10240;
constexpr int F2_STAGE = 18432;
constexpr int F2_BIAS = NSTG * F2_STAGE;     // 55296
constexpr int F2_PERM = F2_BIAS + 512;
constexpr int SMEM2_TOTAL = F2_PERM + 512;   // 56320

constexpr int G1_BLOCKS = (H_ / BN) * MAXT;  // 192
constexpr int SPLITB    = 2048;

// ---------------------------------------------------------------------------
__device__ int g_idx[B_], g_offsets[E_ + 1], g_perm[B_];
__device__ int g_tile_e[MAXT], g_tile_r[MAXT], g_num_tiles;

__device__ __align__(16) __nv_bfloat16 g_zg_h[(B_ + 128) * Z_];
__device__ __align__(16) __nv_bfloat16 g_zg_l[(B_ + 128) * Z_];
__device__ __align__(16) __half       g_hg[(B_ + 128) * H_];
__device__ __align__(16) __nv_bfloat16 g_w1_h[E_ * Z_ * H_];
__device__ __align__(16) __nv_bfloat16 g_w1_l[E_ * Z_ * H_];
__device__ __align__(16) __half       g_w2f[(size_t)E_ * H_ * O_];

// ---------------------------------------------------------------------------
// PTX helpers (arch-agnostic, sm_80+)
// ---------------------------------------------------------------------------
__device__ __forceinline__ uint32_t smem_u32(const void* p) {
    return (uint32_t)__cvta_generic_to_shared(p);
}
__device__ __forceinline__ void cp16(uint32_t dst, const void* src) {
    asm volatile("cp.async.cg.shared.global [%0], [%1], 16;" :: "r"(dst), "l"(src) : "memory");
}
__device__ __forceinline__ void cp_commit() {
    asm volatile("cp.async.commit_group;" ::: "memory");
}
__device__ __forceinline__ void cp_wait2() {
    asm volatile("cp.async.wait_group 2;" ::: "memory");
}
__device__ __forceinline__ void ldsm4(uint32_t* r, uint32_t a) {
    asm volatile("ldmatrix.sync.aligned.m8n8.x4.shared.b16 {%0,%1,%2,%3}, [%4];"
                 : "=r"(r[0]), "=r"(r[1]), "=r"(r[2]), "=r"(r[3]) : "r"(a));
}
__device__ __forceinline__ void ldsm4t(uint32_t* r, uint32_t a) {
    asm volatile("ldmatrix.sync.aligned.m8n8.x4.trans.shared.b16 {%0,%1,%2,%3}, [%4];"
                 : "=r"(r[0]), "=r"(r[1]), "=r"(r[2]), "=r"(r[3]) : "r"(a));
}
__device__ __forceinline__ void mma_bf16(float* d, const uint32_t* a, uint32_t b0, uint32_t b1) {
    asm volatile(
        "mma.sync.aligned.m16n8k16.row.col.f32.bf16.bf16.f32 "
        "{%0,%1,%2,%3}, {%4,%5,%6,%7}, {%8,%9}, {%0,%1,%2,%3};"
        : "+f"(d[0]), "+f"(d[1]), "+f"(d[2]), "+f"(d[3])
        : "r"(a[0]), "r"(a[1]), "r"(a[2]), "r"(a[3]), "r"(b0), "r"(b1));
}
__device__ __forceinline__ void mma_f16(float* d, const uint32_t* a, uint32_t b0, uint32_t b1) {
    asm volatile(
        "mma.sync.aligned.m16n8k16.row.col.f32.f16.f16.f32 "
        "{%0,%1,%2,%3}, {%4,%5,%6,%7}, {%8,%9}, {%0,%1,%2,%3};"
        : "+f"(d[0]), "+f"(d[1]), "+f"(d[2]), "+f"(d[3])
        : "r"(a[0]), "r"(a[1]), "r"(a[2]), "r"(a[3]), "r"(b0), "r"(b1));
}

__device__ __forceinline__ void split4(float4 v, __nv_bfloat162* dh,
                                       __nv_bfloat162* dl, int i) {
    __nv_bfloat16 h0 = __float2bfloat16(v.x), h1 = __float2bfloat16(v.y);
    __nv_bfloat16 h2 = __float2bfloat16(v.z), h3 = __float2bfloat16(v.w);
    __nv_bfloat16 l0 = __float2bfloat16(v.x - __bfloat162float(h0));
    __nv_bfloat16 l1 = __float2bfloat16(v.y - __bfloat162float(h1));
    __nv_bfloat16 l2 = __float2bfloat16(v.z - __bfloat162float(h2));
    __nv_bfloat16 l3 = __float2bfloat16(v.w - __bfloat162float(h3));
    dh[2 * i]     = __nv_bfloat162(h0, h1);
    dh[2 * i + 1] = __nv_bfloat162(h2, h3);
    dl[2 * i]     = __nv_bfloat162(l0, l1);
    dl[2 * i + 1] = __nv_bfloat162(l2, l3);
}

// ---------------------------------------------------------------------------
// Routing (bit-exact vs JAX: exact small integers in fp32, order-independent)
// ---------------------------------------------------------------------------
__global__ void route_kernel(const float* __restrict__ z) {
    int i = blockIdx.x * blockDim.x + threadIdx.x;
    if (i >= B_) return;
    const float* zr = z + (size_t)i * Z_;
    float s = 0.0f;
    #pragma unroll 8
    for (int k = 0; k < Z_; k++)
        s += floorf(fabsf(zr[k]) * 1000.0f);
    g_idx[i] = ((int)s) & (E_ - 1);
}

__global__ void scan_scatter() {
    __shared__ int cnt[E_], cur[E_], offs[E_];
    int t = threadIdx.x;
    if (t < E_) { cnt[t] = 0; cur[t] = 0; }
    __syncthreads();
    for (int i = t; i < B_; i += blockDim.x) atomicAdd(&cnt[g_idx[i]], 1);
    __syncthreads();
    if (t == 0) {
        int o = 0, nt = 0;
        g_offsets[0] = 0;
        for (int e = 0; e < E_; e++) {
            int c = cnt[e];
            offs[e] = o;
            for (int r = 0; r < c; r += BM) { g_tile_e[nt] = e; g_tile_r[nt] = r; nt++; }
            o += c;
            g_offsets[e + 1] = o;
        }
        g_num_tiles = nt;
    }
    __syncthreads();
    for (int i = t; i < B_; i += blockDim.x) {
        int e = g_idx[i];
        int pos = offs[e] + atomicAdd(&cur[e], 1);
        g_perm[pos] = i;
    }
}

// Fused: gather+split z (blocks 0..255) and split W1 (blocks 256..1279)
__global__ void prep_a(const float4* __restrict__ z4, const float4* __restrict__ W1) {
    int bid = blockIdx.x, t = threadIdx.x;
    if (bid < 256) {
        int idx = bid * 256 + t;
        int p = idx >> 5, k4 = idx & 31;
        float4 v = z4[(size_t)g_perm[p] * 32 + k4];
        split4(v, (__nv_bfloat162*)g_zg_h, (__nv_bfloat162*)g_zg_l, idx);
    } else {
        int i = (bid - 256) * 256 + t;
        split4(W1[i], (__nv_bfloat162*)g_w1_h, (__nv_bfloat162*)g_w1_l, i);
    }
}

// ---------------------------------------------------------------------------
// GEMM1 tile: bf16 3-term (z @ W1), relu, fp16 output (perm-order rows)
// ---------------------------------------------------------------------------
__device__ void moe_gemm_tile1(const float* __restrict__ bias, int nblk, int tile,
                               char* smem) {
    const int K = Z_, NTOT = H_;
    const int e      = g_tile_e[tile];
    const int row0   = g_tile_r[tile];
    const int off    = g_offsets[e];
    const int cnt    = g_offsets[e + 1] - off;
    const int mvalid = min(BM, cnt - row0);
    const int n0     = nblk * BN;
    const int arow0  = off + row0;

    const uint32_t sb = smem_u32(smem);
    float* sBias = (float*)(smem + OFF_BIAS);
    const int t = threadIdx.x;
    const int lane = t & 31;
    const int wid = t >> 5;

    if (t < 128) sBias[t] = bias[(size_t)e * NTOT + n0 + t];

    const __nv_bfloat16* BhE = g_w1_h + (size_t)e * NTOT * K;
    const __nv_bfloat16* BlE = g_w1_l + (size_t)e * NTOT * K;
    const int NS = K / BK;

    auto load_stage = [&](int s) {
        const int k0 = s * BK;
        const uint32_t base = sb + (s % NSTG) * STAGE;
        #pragma unroll
        for (int i = 0; i < 2; i++) {
            int idx = t + i * 256;
            int r = idx >> 2, kc = idx & 3;
            uint32_t d = (uint32_t)(r * 80 + kc * 16);
            size_t so = (size_t)(arow0 + r) * K + k0 + kc * 8;
            cp16(base + OFF_AH + d, g_zg_h + so);
            cp16(base + OFF_AL + d, g_zg_l + so);
        }
        #pragma unroll
        for (int i = 0; i < 2; i++) {
            int idx = t + i * 256;
            int kr = idx >> 4, nc = idx & 15;
            uint32_t d = (uint32_t)(kr * 256 + nc * 16) ^ (uint32_t)((kr & 15) << 4);
            size_t so = (size_t)(k0 + kr) * NTOT + n0 + nc * 8;
            cp16(base + OFF_BH + d, BhE + so);
            cp16(base + OFF_BL + d, BlE + so);
        }
        cp_commit();
    };

    const int wm0 = (wid & 3) * 32;
    const int wn0 = (wid >> 2) * 64;

    float acc[2][8][4];
    #pragma unroll
    for (int a = 0; a < 2; a++)
        #pragma unroll
        for (int b = 0; b < 8; b++)
            #pragma unroll
            for (int c = 0; c < 4; c++) acc[a][b][c] = 0.0f;

    load_stage(0);
    load_stage(1);
    load_stage(2);

    for (int s = 0; s < NS; s++) {
        cp_wait2();
        __syncthreads();
        const uint32_t base = sb + (s % NSTG) * STAGE;
        #pragma unroll
        for (int kk = 0; kk < 2; kk++) {
            uint32_t a_h[2][4], a_l[2][4];
            #pragma unroll
            for (int mi = 0; mi < 2; mi++) {
                uint32_t ad = base + OFF_AH +
                    (uint32_t)((wm0 + mi * 16 + (lane & 15)) * 80 + (lane >> 4) * 16 + kk * 32);
                ldsm4(a_h[mi], ad);
                ldsm4(a_l[mi], ad + (OFF_AL - OFF_AH));
            }
            #pragma unroll
            for (int pp = 0; pp < 2; pp++) {
                uint32_t b_h[2][4], b_l[2][4];
                #pragma unroll
                for (int q = 0; q < 2; q++) {
                    int p = pp * 2 + q;
                    uint32_t nb = (uint32_t)((wn0 + p * 16 + (lane >> 4) * 8) * 2);
                    uint32_t bd = base + OFF_BH +
                        (((uint32_t)((kk * 16 + (lane & 15)) * 256) + nb) ^ (uint32_t)((lane & 15) << 4));
                    ldsm4t(b_h[q], bd);
                    ldsm4t(b_l[q], bd + (OFF_BL - OFF_BH));
                }
                #pragma unroll
                for (int mi = 0; mi < 2; mi++)
                    #pragma unroll
                    for (int nq = 0; nq < 4; nq++) {
                        int ni = pp * 4 + nq;
                        int q = nq >> 1, hh = (nq & 1) * 2;
                        mma_bf16(acc[mi][ni], a_h[mi], b_h[q][hh], b_h[q][hh + 1]);
                        mma_bf16(acc[mi][ni], a_h[mi], b_l[q][hh], b_l[q][hh + 1]);
                        mma_bf16(acc[mi][ni], a_l[mi], b_h[q][hh], b_h[q][hh + 1]);
                    }
            }
        }
        __syncthreads();
        if (s + 3 < NS) load_stage(s + 3);
        else cp_commit();
    }

    #pragma unroll
    for (int mi = 0; mi < 2; mi++) {
        #pragma unroll
        for (int half = 0; half < 2; half++) {
            int r = wm0 + mi * 16 + (lane >> 2) + half * 8;
            if (r >= mvalid) continue;
            #pragma unroll
            for (int ni = 0; ni < 8; ni++) {
                int cl = wn0 + ni * 8 + (lane & 3) * 2;
                float v0 = fmaxf(acc[mi][ni][half * 2]     + sBias[cl], 0.0f);
                float v1 = fmaxf(acc[mi][ni][half * 2 + 1] + sBias[cl + 1], 0.0f);
                size_t p = (size_t)(arow0 + r) * NTOT + n0 + cl;
                *(__half2*)(g_hg + p) =
                    __halves2half2(__float2half_rn(v0), __float2half_rn(v1));
            }
        }
    }
}

// ---------------------------------------------------------------------------
// GEMM2 tile: fp16 single-term (h @ W2), bias, fp32 scatter to original rows
// ---------------------------------------------------------------------------
__device__ void moe_gemm_tile2(const float* __restrict__ bias, float* __restrict__ outf,
                               int nblk, int tile, char* smem) {
    const int K = H_, NTOT = O_;
    const int e      = g_tile_e[tile];
    const int row0   = g_tile_r[tile];
    const int off    = g_offsets[e];
    const int cnt    = g_offsets[e + 1] - off;
    const int mvalid = min(BM, cnt - row0);
    const int n0     = nblk * BN;
    const int arow0  = off + row0;

    const uint32_t sb = smem_u32(smem);
    float* sBias = (float*)(smem + F2_BIAS);
    int*   sPerm = (int*)(smem + F2_PERM);

    const int t = threadIdx.x;
    const int lane = t & 31;
    const int wid = t >> 5;

    if (t < 128) {
        sBias[t] = bias[(size_t)e * NTOT + n0 + t];
        sPerm[t] = (t < mvalid) ? g_perm[arow0 + t] : 0;
    }

    const __half* BE = g_w2f + (size_t)e * NTOT * K;
    const int NS = K / BK;

    auto load_stage = [&](int s) {
        const int k0 = s * BK;
        const uint32_t base = sb + (s % NSTG) * F2_STAGE;
        #pragma unroll
        for (int i = 0; i < 2; i++) {               // A: 512 chunks of 16B
            int idx = t + i * 256;
            int r = idx >> 2, kc = idx & 3;
            uint32_t d = (uint32_t)(r * 80 + kc * 16);
            cp16(base + F2_A + d, g_hg + (size_t)(arow0 + r) * K + k0 + kc * 8);
        }
        #pragma unroll
        for (int i = 0; i < 2; i++) {               // B: 512 chunks of 16B
            int idx = t + i * 256;
            int kr = idx >> 4, nc = idx & 15;
            uint32_t d = (uint32_t)(kr * 256 + nc * 16) ^ (uint32_t)((kr & 15) << 4);
            cp16(base + F2_B + d, BE + (size_t)(k0 + kr) * NTOT + n0 + nc * 8);
        }
        cp_commit();
    };

    const int wm0 = (wid & 3) * 32;
    const int wn0 = (wid >> 2) * 64;

    float acc[2][8][4];
    #pragma unroll
    for (int a = 0; a < 2; a++)
        #pragma unroll
        for (int b = 0; b < 8; b++)
            #pragma unroll
            for (int c = 0; c < 4; c++) acc[a][b][c] = 0.0f;

    load_stage(0);
    load_stage(1);
    load_stage(2);

    for (int s = 0; s < NS; s++) {
        cp_wait2();
        __syncthreads();
        const uint32_t base = sb + (s % NSTG) * F2_STAGE;
        #pragma unroll
        for (int kk = 0; kk < 2; kk++) {
            uint32_t a[2][4];
            #pragma unroll
            for (int mi = 0; mi < 2; mi++) {
                uint32_t ad = base + F2_A +
                    (uint32_t)((wm0 + mi * 16 + (lane & 15)) * 80 + (lane >> 4) * 16 + kk * 32);
                ldsm4(a[mi], ad);
            }
            uint32_t b[4][4];
            #pragma unroll
            for (int p = 0; p < 4; p++) {
                uint32_t nb = (uint32_t)((wn0 + p * 16 + (lane >> 4) * 8) * 2);
                uint32_t bd = base + F2_B +
                    (((uint32_t)((kk * 16 + (lane & 15)) * 256) + nb) ^ (uint32_t)((lane & 15) << 4));
                ldsm4t(b[p], bd);
            }
            #pragma unroll
            for (int mi = 0; mi < 2; mi++)
                #pragma unroll
                for (int ni = 0; ni < 8; ni++) {
                    int p = ni >> 1, hh = (ni & 1) * 2;
                    mma_f16(acc[mi][ni], a[mi], b[p][hh], b[p][hh + 1]);
                }
        }
        __syncthreads();
        if (s + 3 < NS) load_stage(s + 3);
        else cp_commit();
    }

    #pragma unroll
    for (int mi = 0; mi < 2; mi++) {
        #pragma unroll
        for (int half = 0; half < 2; half++) {
            int r = wm0 + mi * 16 + (lane >> 2) + half * 8;
            if (r >= mvalid) continue;
            #pragma unroll
            for (int ni = 0; ni < 8; ni++) {
                int cl = wn0 + ni * 8 + (lane & 3) * 2;
                float v0 = acc[mi][ni][half * 2]     + sBias[cl];
                float v1 = acc[mi][ni][half * 2 + 1] + sBias[cl + 1];
                size_t p = (size_t)sPerm[r] * NTOT + n0 + cl;
                *(float2*)(outf + p) = make_float2(v0, v1);
            }
        }
    }
}

// ---------------------------------------------------------------------------
// fusedB: layer-1 GEMM (blocks 0..191) overlapped with W2 fp16 convert (rest)
// ---------------------------------------------------------------------------
__global__ __launch_bounds__(256, 2)
void fusedB(const float* __restrict__ b1, const float4* __restrict__ W2) {
    extern __shared__ char smem[];
    int bid = blockIdx.x;
    if (bid < G1_BLOCKS) {
        int tile = bid >> 3;
        if (tile >= g_num_tiles) return;
        moe_gemm_tile1(b1, bid & 7, tile, smem);
    } else {
        const int n4 = (int)((size_t)E_ * H_ * O_ / 4);
        __half2* dst = (__half2*)g_w2f;
        for (int i = (bid - G1_BLOCKS) * 256 + threadIdx.x; i < n4; i += SPLITB * 256) {
            float4 v = W2[i];
            dst[2 * i]     = __halves2half2(__float2half_rn(v.x), __float2half_rn(v.y));
            dst[2 * i + 1] = __halves2half2(__float2half_rn(v.z), __float2half_rn(v.w));
        }
    }
}

__global__ __launch_bounds__(256, 2)
void moe_mma2(const float* __restrict__ b2, float* __restrict__ out) {
    extern __shared__ char smem[];
    int tile = blockIdx.y;
    if (tile >= g_num_tiles) return;
    moe_gemm_tile2(b2, out, blockIdx.x, tile, smem);
}

// ---------------------------------------------------------------------------
extern "C" void kernel_launch(void* const* d_in, const int* in_sizes, int n_in,
                              void* d_out, int out_size) {
    const float* z  = (const float*)d_in[0];
    const float* W1 = (const float*)d_in[1];
    const float* b1 = (const float*)d_in[2];
    const float* W2 = (const float*)d_in[3];
    const float* b2 = (const float*)d_in[4];
    float* out = (float*)d_out;

    cudaFuncSetAttribute(fusedB, cudaFuncAttributeMaxDynamicSharedMemorySize, SMEM_TOTAL);
    cudaFuncSetAttribute(moe_mma2, cudaFuncAttributeMaxDynamicSharedMemorySize, SMEM2_TOTAL);

    route_kernel<<<B_ / 256, 256>>>(z);
    scan_scatter<<<1, 1024>>>();
    prep_a<<<1280, 256>>>((const float4*)z, (const float4*)W1);
    fusedB<<<G1_BLOCKS + SPLITB, 256, SMEM_TOTAL>>>(b1, (const float4*)W2);
    moe_mma2<<<dim3(O_ / BN, MAXT), 256, SMEM2_TOTAL>>>(b2, out);
}

// round 10
// speedup vs baseline: 4.4546x; 1.0171x over previous
#include <cuda_runtime.h>
#include <cuda_bf16.h>
#include <cuda_fp16.h>
#include <cstdint>

// ---------------------------------------------------------------------------
constexpr int B_ = 2048, Z_ = 128, H_ = 1024, O_ = 3072, E_ = 8;
constexpr int MAXT = B_ / 128 + E_;   // 24
constexpr int BM = 128, BN = 128, BK = 32;
constexpr int NSTG = 3;

// GEMM1 (bf16 3-term) stage layout: A hi/lo 128x32 (80B-stride), B hi/lo 32x128
constexpr int OFF_AH = 0;
constexpr int OFF_AL = 10240;
constexpr int OFF_BH = 20480;
constexpr int OFF_BL = 28672;
constexpr int STAGE  = 36864;
constexpr int OFF_BIAS = NSTG * STAGE;       // 110592
constexpr int OFF_PERM = OFF_BIAS + 512;
constexpr int SMEM_TOTAL = OFF_PERM + 512;   // 111616

// GEMM2 (fp16 single-term) stage: A 128x32 fp16 (80B-stride), B 32x128 fp16
constexpr int F2_A  = 0;
constexpr int F2_B  = 10240;
constexpr int F2_STAGE = 18432;
constexpr int F2_BIAS = NSTG * F2_STAGE;     // 55296
constexpr int F2_PERM = F2_BIAS + 512;
constexpr int SMEM2_TOTAL = F2_PERM + 512;   // 56320

constexpr int G1_BLOCKS = (H_ / BN) * MAXT;  // 192
constexpr int SPLITB    = 2048;
constexpr int W1_BLOCKS = E_ * Z_ * H_ / 4 / 256;   // 1024

// ---------------------------------------------------------------------------
__device__ int g_idx[B_], g_offsets[E_ + 1], g_perm[B_];
__device__ int g_tile_e[MAXT], g_tile_r[MAXT], g_num_tiles;

__device__ __align__(16) __nv_bfloat16 g_zg_h[(B_ + 128) * Z_];
__device__ __align__(16) __nv_bfloat16 g_zg_l[(B_ + 128) * Z_];
__device__ __align__(16) __half       g_hg[(B_ + 128) * H_];
__device__ __align__(16) __nv_bfloat16 g_w1_h[E_ * Z_ * H_];
__device__ __align__(16) __nv_bfloat16 g_w1_l[E_ * Z_ * H_];
__device__ __align__(16) __half       g_w2f[(size_t)E_ * H_ * O_];

// ---------------------------------------------------------------------------
// PTX helpers (arch-agnostic, sm_80+)
// ---------------------------------------------------------------------------
__device__ __forceinline__ uint32_t smem_u32(const void* p) {
    return (uint32_t)__cvta_generic_to_shared(p);
}
__device__ __forceinline__ void cp16(uint32_t dst, const void* src) {
    asm volatile("cp.async.cg.shared.global [%0], [%1], 16;" :: "r"(dst), "l"(src) : "memory");
}
__device__ __forceinline__ void cp_commit() {
    asm volatile("cp.async.commit_group;" ::: "memory");
}
__device__ __forceinline__ void cp_wait2() {
    asm volatile("cp.async.wait_group 2;" ::: "memory");
}
__device__ __forceinline__ void ldsm4(uint32_t* r, uint32_t a) {
    asm volatile("ldmatrix.sync.aligned.m8n8.x4.shared.b16 {%0,%1,%2,%3}, [%4];"
                 : "=r"(r[0]), "=r"(r[1]), "=r"(r[2]), "=r"(r[3]) : "r"(a));
}
__device__ __forceinline__ void ldsm4t(uint32_t* r, uint32_t a) {
    asm volatile("ldmatrix.sync.aligned.m8n8.x4.trans.shared.b16 {%0,%1,%2,%3}, [%4];"
                 : "=r"(r[0]), "=r"(r[1]), "=r"(r[2]), "=r"(r[3]) : "r"(a));
}
__device__ __forceinline__ void mma_bf16(float* d, const uint32_t* a, uint32_t b0, uint32_t b1) {
    asm volatile(
        "mma.sync.aligned.m16n8k16.row.col.f32.bf16.bf16.f32 "
        "{%0,%1,%2,%3}, {%4,%5,%6,%7}, {%8,%9}, {%0,%1,%2,%3};"
        : "+f"(d[0]), "+f"(d[1]), "+f"(d[2]), "+f"(d[3])
        : "r"(a[0]), "r"(a[1]), "r"(a[2]), "r"(a[3]), "r"(b0), "r"(b1));
}
__device__ __forceinline__ void mma_f16(float* d, const uint32_t* a, uint32_t b0, uint32_t b1) {
    asm volatile(
        "mma.sync.aligned.m16n8k16.row.col.f32.f16.f16.f32 "
        "{%0,%1,%2,%3}, {%4,%5,%6,%7}, {%8,%9}, {%0,%1,%2,%3};"
        : "+f"(d[0]), "+f"(d[1]), "+f"(d[2]), "+f"(d[3])
        : "r"(a[0]), "r"(a[1]), "r"(a[2]), "r"(a[3]), "r"(b0), "r"(b1));
}

__device__ __forceinline__ void split4(float4 v, __nv_bfloat162* dh,
                                       __nv_bfloat162* dl, int i) {
    __nv_bfloat16 h0 = __float2bfloat16(v.x), h1 = __float2bfloat16(v.y);
    __nv_bfloat16 h2 = __float2bfloat16(v.z), h3 = __float2bfloat16(v.w);
    __nv_bfloat16 l0 = __float2bfloat16(v.x - __bfloat162float(h0));
    __nv_bfloat16 l1 = __float2bfloat16(v.y - __bfloat162float(h1));
    __nv_bfloat16 l2 = __float2bfloat16(v.z - __bfloat162float(h2));
    __nv_bfloat16 l3 = __float2bfloat16(v.w - __bfloat162float(h3));
    dh[2 * i]     = __nv_bfloat162(h0, h1);
    dh[2 * i + 1] = __nv_bfloat162(h2, h3);
    dl[2 * i]     = __nv_bfloat162(l0, l1);
    dl[2 * i + 1] = __nv_bfloat162(l2, l3);
}

__device__ __forceinline__ void cvt_f16_store8(__half2* dst, int i, float4 v) {
    __half2 a = __halves2half2(__float2half_rn(v.x), __float2half_rn(v.y));
    __half2 b = __halves2half2(__float2half_rn(v.z), __float2half_rn(v.w));
    uint2 u;
    u.x = *(uint32_t*)&a;
    u.y = *(uint32_t*)&b;
    *(uint2*)(dst + 2 * i) = u;
}

// ---------------------------------------------------------------------------
// route (blocks 0..7) fused with W1 split (blocks 8..) — W1 split is
// routing-independent, so it overlaps the routing critical path.
// Routing is bit-exact vs JAX (exact small integers in fp32).
// ---------------------------------------------------------------------------
__global__ void route_w1(const float* __restrict__ z, const float4* __restrict__ W1) {
    int bid = blockIdx.x, t = threadIdx.x;
    if (bid < 8) {
        int i = bid * 256 + t;
        const float* zr = z + (size_t)i * Z_;
        float s = 0.0f;
        #pragma unroll 8
        for (int k = 0; k < Z_; k++)
            s += floorf(fabsf(zr[k]) * 1000.0f);
        g_idx[i] = ((int)s) & (E_ - 1);
    } else {
        int i = (bid - 8) * 256 + t;   // < 262144
        split4(W1[i], (__nv_bfloat162*)g_w1_h, (__nv_bfloat162*)g_w1_l, i);
    }
}

__global__ void scan_scatter() {
    __shared__ int cnt[E_], cur[E_], offs[E_];
    int t = threadIdx.x;
    if (t < E_) { cnt[t] = 0; cur[t] = 0; }
    __syncthreads();
    for (int i = t; i < B_; i += blockDim.x) atomicAdd(&cnt[g_idx[i]], 1);
    __syncthreads();
    if (t == 0) {
        int o = 0, nt = 0;
        g_offsets[0] = 0;
        for (int e = 0; e < E_; e++) {
            int c = cnt[e];
            offs[e] = o;
            for (int r = 0; r < c; r += BM) { g_tile_e[nt] = e; g_tile_r[nt] = r; nt++; }
            o += c;
            g_offsets[e + 1] = o;
        }
        g_num_tiles = nt;
    }
    __syncthreads();
    for (int i = t; i < B_; i += blockDim.x) {
        int e = g_idx[i];
        int pos = offs[e] + atomicAdd(&cur[e], 1);
        g_perm[pos] = i;
    }
}

// z gather + bf16 hi/lo split only (perm-dependent)
__global__ void prep_z(const float4* __restrict__ z4) {
    int idx = blockIdx.x * 256 + threadIdx.x;    // 256 blocks
    int p = idx >> 5, k4 = idx & 31;
    float4 v = z4[(size_t)g_perm[p] * 32 + k4];
    split4(v, (__nv_bfloat162*)g_zg_h, (__nv_bfloat162*)g_zg_l, idx);
}

// ---------------------------------------------------------------------------
// GEMM1 tile: bf16 3-term (z @ W1), relu, fp16 output (perm-order rows)
// ---------------------------------------------------------------------------
__device__ void moe_gemm_tile1(const float* __restrict__ bias, int nblk, int tile,
                               char* smem) {
    const int K = Z_, NTOT = H_;
    const int e      = g_tile_e[tile];
    const int row0   = g_tile_r[tile];
    const int off    = g_offsets[e];
    const int cnt    = g_offsets[e + 1] - off;
    const int mvalid = min(BM, cnt - row0);
    const int n0     = nblk * BN;
    const int arow0  = off + row0;

    const uint32_t sb = smem_u32(smem);
    float* sBias = (float*)(smem + OFF_BIAS);
    const int t = threadIdx.x;
    const int lane = t & 31;
    const int wid = t >> 5;

    if (t < 128) sBias[t] = bias[(size_t)e * NTOT + n0 + t];

    const __nv_bfloat16* BhE = g_w1_h + (size_t)e * NTOT * K;
    const __nv_bfloat16* BlE = g_w1_l + (size_t)e * NTOT * K;
    const int NS = K / BK;

    auto load_stage = [&](int s) {
        const int k0 = s * BK;
        const uint32_t base = sb + (s % NSTG) * STAGE;
        #pragma unroll
        for (int i = 0; i < 2; i++) {
            int idx = t + i * 256;
            int r = idx >> 2, kc = idx & 3;
            uint32_t d = (uint32_t)(r * 80 + kc * 16);
            size_t so = (size_t)(arow0 + r) * K + k0 + kc * 8;
            cp16(base + OFF_AH + d, g_zg_h + so);
            cp16(base + OFF_AL + d, g_zg_l + so);
        }
        #pragma unroll
        for (int i = 0; i < 2; i++) {
            int idx = t + i * 256;
            int kr = idx >> 4, nc = idx & 15;
            uint32_t d = (uint32_t)(kr * 256 + nc * 16) ^ (uint32_t)((kr & 15) << 4);
            size_t so = (size_t)(k0 + kr) * NTOT + n0 + nc * 8;
            cp16(base + OFF_BH + d, BhE + so);
            cp16(base + OFF_BL + d, BlE + so);
        }
        cp_commit();
    };

    const int wm0 = (wid & 3) * 32;
    const int wn0 = (wid >> 2) * 64;

    float acc[2][8][4];
    #pragma unroll
    for (int a = 0; a < 2; a++)
        #pragma unroll
        for (int b = 0; b < 8; b++)
            #pragma unroll
            for (int c = 0; c < 4; c++) acc[a][b][c] = 0.0f;

    load_stage(0);
    load_stage(1);
    load_stage(2);

    for (int s = 0; s < NS; s++) {
        cp_wait2();
        __syncthreads();
        const uint32_t base = sb + (s % NSTG) * STAGE;
        #pragma unroll
        for (int kk = 0; kk < 2; kk++) {
            uint32_t a_h[2][4], a_l[2][4];
            #pragma unroll
            for (int mi = 0; mi < 2; mi++) {
                uint32_t ad = base + OFF_AH +
                    (uint32_t)((wm0 + mi * 16 + (lane & 15)) * 80 + (lane >> 4) * 16 + kk * 32);
                ldsm4(a_h[mi], ad);
                ldsm4(a_l[mi], ad + (OFF_AL - OFF_AH));
            }
            #pragma unroll
            for (int pp = 0; pp < 2; pp++) {
                uint32_t b_h[2][4], b_l[2][4];
                #pragma unroll
                for (int q = 0; q < 2; q++) {
                    int p = pp * 2 + q;
                    uint32_t nb = (uint32_t)((wn0 + p * 16 + (lane >> 4) * 8) * 2);
                    uint32_t bd = base + OFF_BH +
                        (((uint32_t)((kk * 16 + (lane & 15)) * 256) + nb) ^ (uint32_t)((lane & 15) << 4));
                    ldsm4t(b_h[q], bd);
                    ldsm4t(b_l[q], bd + (OFF_BL - OFF_BH));
                }
                #pragma unroll
                for (int mi = 0; mi < 2; mi++)
                    #pragma unroll
                    for (int nq = 0; nq < 4; nq++) {
                        int ni = pp * 4 + nq;
                        int q = nq >> 1, hh = (nq & 1) * 2;
                        mma_bf16(acc[mi][ni], a_h[mi], b_h[q][hh], b_h[q][hh + 1]);
                        mma_bf16(acc[mi][ni], a_h[mi], b_l[q][hh], b_l[q][hh + 1]);
                        mma_bf16(acc[mi][ni], a_l[mi], b_h[q][hh], b_h[q][hh + 1]);
                    }
            }
        }
        __syncthreads();
        if (s + 3 < NS) load_stage(s + 3);
        else cp_commit();
    }

    #pragma unroll
    for (int mi = 0; mi < 2; mi++) {
        #pragma unroll
        for (int half = 0; half < 2; half++) {
            int r = wm0 + mi * 16 + (lane >> 2) + half * 8;
            if (r >= mvalid) continue;
            #pragma unroll
            for (int ni = 0; ni < 8; ni++) {
                int cl = wn0 + ni * 8 + (lane & 3) * 2;
                float v0 = fmaxf(acc[mi][ni][half * 2]     + sBias[cl], 0.0f);
                float v1 = fmaxf(acc[mi][ni][half * 2 + 1] + sBias[cl + 1], 0.0f);
                size_t p = (size_t)(arow0 + r) * NTOT + n0 + cl;
                *(__half2*)(g_hg + p) =
                    __halves2half2(__float2half_rn(v0), __float2half_rn(v1));
            }
        }
    }
}

// ---------------------------------------------------------------------------
// GEMM2 tile: fp16 single-term (h @ W2), bias, fp32 scatter to original rows
// ---------------------------------------------------------------------------
__device__ void moe_gemm_tile2(const float* __restrict__ bias, float* __restrict__ outf,
                               int nblk, int tile, char* smem) {
    const int K = H_, NTOT = O_;
    const int e      = g_tile_e[tile];
    const int row0   = g_tile_r[tile];
    const int off    = g_offsets[e];
    const int cnt    = g_offsets[e + 1] - off;
    const int mvalid = min(BM, cnt - row0);
    const int n0     = nblk * BN;
    const int arow0  = off + row0;

    const uint32_t sb = smem_u32(smem);
    float* sBias = (float*)(smem + F2_BIAS);
    int*   sPerm = (int*)(smem + F2_PERM);

    const int t = threadIdx.x;
    const int lane = t & 31;
    const int wid = t >> 5;

    if (t < 128) {
        sBias[t] = bias[(size_t)e * NTOT + n0 + t];
        sPerm[t] = (t < mvalid) ? g_perm[arow0 + t] : 0;
    }

    const __half* BE = g_w2f + (size_t)e * NTOT * K;
    const int NS = K / BK;

    auto load_stage = [&](int s) {
        const int k0 = s * BK;
        const uint32_t base = sb + (s % NSTG) * F2_STAGE;
        #pragma unroll
        for (int i = 0; i < 2; i++) {               // A: 512 chunks of 16B
            int idx = t + i * 256;
            int r = idx >> 2, kc = idx & 3;
            uint32_t d = (uint32_t)(r * 80 + kc * 16);
            cp16(base + F2_A + d, g_hg + (size_t)(arow0 + r) * K + k0 + kc * 8);
        }
        #pragma unroll
        for (int i = 0; i < 2; i++) {               // B: 512 chunks of 16B
            int idx = t + i * 256;
            int kr = idx >> 4, nc = idx & 15;
            uint32_t d = (uint32_t)(kr * 256 + nc * 16) ^ (uint32_t)((kr & 15) << 4);
            cp16(base + F2_B + d, BE + (size_t)(k0 + kr) * NTOT + n0 + nc * 8);
        }
        cp_commit();
    };

    const int wm0 = (wid & 3) * 32;
    const int wn0 = (wid >> 2) * 64;

    float acc[2][8][4];
    #pragma unroll
    for (int a = 0; a < 2; a++)
        #pragma unroll
        for (int b = 0; b < 8; b++)
            #pragma unroll
            for (int c = 0; c < 4; c++) acc[a][b][c] = 0.0f;

    load_stage(0);
    load_stage(1);
    load_stage(2);

    for (int s = 0; s < NS; s++) {
        cp_wait2();
        __syncthreads();
        const uint32_t base = sb + (s % NSTG) * F2_STAGE;
        #pragma unroll
        for (int kk = 0; kk < 2; kk++) {
            uint32_t a[2][4];
            #pragma unroll
            for (int mi = 0; mi < 2; mi++) {
                uint32_t ad = base + F2_A +
                    (uint32_t)((wm0 + mi * 16 + (lane & 15)) * 80 + (lane >> 4) * 16 + kk * 32);
                ldsm4(a[mi], ad);
            }
            uint32_t b[4][4];
            #pragma unroll
            for (int p = 0; p < 4; p++) {
                uint32_t nb = (uint32_t)((wn0 + p * 16 + (lane >> 4) * 8) * 2);
                uint32_t bd = base + F2_B +
                    (((uint32_t)((kk * 16 + (lane & 15)) * 256) + nb) ^ (uint32_t)((lane & 15) << 4));
                ldsm4t(b[p], bd);
            }
            #pragma unroll
            for (int mi = 0; mi < 2; mi++)
                #pragma unroll
                for (int ni = 0; ni < 8; ni++) {
                    int p = ni >> 1, hh = (ni & 1) * 2;
                    mma_f16(acc[mi][ni], a[mi], b[p][hh], b[p][hh + 1]);
                }
        }
        __syncthreads();
        if (s + 3 < NS) load_stage(s + 3);
        else cp_commit();
    }

    #pragma unroll
    for (int mi = 0; mi < 2; mi++) {
        #pragma unroll
        for (int half = 0; half < 2; half++) {
            int r = wm0 + mi * 16 + (lane >> 2) + half * 8;
            if (r >= mvalid) continue;
            #pragma unroll
            for (int ni = 0; ni < 8; ni++) {
                int cl = wn0 + ni * 8 + (lane & 3) * 2;
                float v0 = acc[mi][ni][half * 2]     + sBias[cl];
                float v1 = acc[mi][ni][half * 2 + 1] + sBias[cl + 1];
                size_t p = (size_t)sPerm[r] * NTOT + n0 + cl;
                *(float2*)(outf + p) = make_float2(v0, v1);
            }
        }
    }
}

// ---------------------------------------------------------------------------
// fusedB: layer-1 GEMM (blocks 0..191) overlapped with W2 fp16 convert (rest).
// Convert uses 4-way independent loads per iteration (MLP ~4) + 8B stores.
// ---------------------------------------------------------------------------
__global__ __launch_bounds__(256, 2)
void fusedB(const float* __restrict__ b1, const float4* __restrict__ W2) {
    extern __shared__ char smem[];
    int bid = blockIdx.x;
    if (bid < G1_BLOCKS) {
        int tile = bid >> 3;
        if (tile >= g_num_tiles) return;
        moe_gemm_tile1(b1, bid & 7, tile, smem);
    } else {
        // n4 = 6291456 = SPLITB*256*12; 3 outer iters of 4 independent loads
        const int stride = SPLITB * 256;
        __half2* dst = (__half2*)g_w2f;
        int base = (bid - G1_BLOCKS) * 256 + threadIdx.x;
        #pragma unroll
        for (int o = 0; o < 3; o++) {
            int i0 = base + (o * 4) * stride;
            float4 v0 = W2[i0];
            float4 v1 = W2[i0 + stride];
            float4 v2 = W2[i0 + 2 * stride];
            float4 v3 = W2[i0 + 3 * stride];
            cvt_f16_store8(dst, i0,              v0);
            cvt_f16_store8(dst, i0 + stride,     v1);
            cvt_f16_store8(dst, i0 + 2 * stride, v2);
            cvt_f16_store8(dst, i0 + 3 * stride, v3);
        }
    }
}

__global__ __launch_bounds__(256, 2)
void moe_mma2(const float* __restrict__ b2, float* __restrict__ out) {
    extern __shared__ char smem[];
    int tile = blockIdx.y;
    if (tile >= g_num_tiles) return;
    moe_gemm_tile2(b2, out, blockIdx.x, tile, smem);
}

// ---------------------------------------------------------------------------
extern "C" void kernel_launch(void* const* d_in, const int* in_sizes, int n_in,
                              void* d_out, int out_size) {
    const float* z  = (const float*)d_in[0];
    const float* W1 = (const float*)d_in[1];
    const float* b1 = (const float*)d_in[2];
    const float* W2 = (const float*)d_in[3];
    const float* b2 = (const float*)d_in[4];
    float* out = (float*)d_out;

    cudaFuncSetAttribute(fusedB, cudaFuncAttributeMaxDynamicSharedMemorySize, SMEM_TOTAL);
    cudaFuncSetAttribute(moe_mma2, cudaFuncAttributeMaxDynamicSharedMemorySize, SMEM2_TOTAL);

    route_w1<<<8 + W1_BLOCKS, 256>>>(z, (const float4*)W1);
    scan_scatter<<<1, 1024>>>();
    prep_z<<<256, 256>>>((const float4*)z);
    fusedB<<<G1_BLOCKS + SPLITB, 256, SMEM_TOTAL>>>(b1, (const float4*)W2);
    moe_mma2<<<dim3(O_ / BN, MAXT), 256, SMEM2_TOTAL>>>(b2, out);
}

// round 11
// speedup vs baseline: 4.5131x; 1.0131x over previous
#include <cuda_runtime.h>
#include <cuda_bf16.h>
#include <cuda_fp16.h>
#include <cstdint>

// ---------------------------------------------------------------------------
constexpr int B_ = 2048, Z_ = 128, H_ = 1024, O_ = 3072, E_ = 8;
constexpr int MAXT = B_ / 128 + E_;   // 24
constexpr int BM = 128, BN = 128, BK = 32;
constexpr int NSTG = 3;

// GEMM1 (bf16 3-term) stage layout: A hi/lo 128x32 (80B-stride), B hi/lo 32x128
constexpr int OFF_AH = 0;
constexpr int OFF_AL = 10240;
constexpr int OFF_BH = 20480;
constexpr int OFF_BL = 28672;
constexpr int STAGE  = 36864;
constexpr int OFF_BIAS = NSTG * STAGE;       // 110592
constexpr int OFF_PERM = OFF_BIAS + 512;
constexpr int SMEM_TOTAL = OFF_PERM + 512;   // 111616

// GEMM2 (fp16 single-term) stage: A 128x32 fp16 (80B-stride), B 32x128 fp16
constexpr int F2_A  = 0;
constexpr int F2_B  = 10240;
constexpr int F2_STAGE = 18432;
constexpr int F2_BIAS = NSTG * F2_STAGE;     // 55296
constexpr int F2_PERM = F2_BIAS + 512;
constexpr int SMEM2_TOTAL = F2_PERM + 512;   // 56320

constexpr int G1_BLOCKS = (H_ / BN) * MAXT;  // 192
constexpr int CONVB    = 2048;               // W2 convert blocks
constexpr int W1_BLOCKS = E_ * Z_ * H_ / 4 / 256;   // 1024

// ---------------------------------------------------------------------------
__device__ int g_idx[B_], g_offsets[E_ + 1], g_perm[B_];
__device__ int g_tile_e[MAXT], g_tile_r[MAXT], g_num_tiles;

__device__ __align__(16) __nv_bfloat16 g_zg_h[(B_ + 128) * Z_];
__device__ __align__(16) __nv_bfloat16 g_zg_l[(B_ + 128) * Z_];
__device__ __align__(16) __half       g_hg[(B_ + 128) * H_];
__device__ __align__(16) __nv_bfloat16 g_w1_h[E_ * Z_ * H_];
__device__ __align__(16) __nv_bfloat16 g_w1_l[E_ * Z_ * H_];
__device__ __align__(16) __half       g_w2f[(size_t)E_ * H_ * O_];

// ---------------------------------------------------------------------------
// PTX helpers (arch-agnostic, sm_80+)
// ---------------------------------------------------------------------------
__device__ __forceinline__ uint32_t smem_u32(const void* p) {
    return (uint32_t)__cvta_generic_to_shared(p);
}
__device__ __forceinline__ void cp16(uint32_t dst, const void* src) {
    asm volatile("cp.async.cg.shared.global [%0], [%1], 16;" :: "r"(dst), "l"(src) : "memory");
}
__device__ __forceinline__ void cp_commit() {
    asm volatile("cp.async.commit_group;" ::: "memory");
}
__device__ __forceinline__ void cp_wait2() {
    asm volatile("cp.async.wait_group 2;" ::: "memory");
}
__device__ __forceinline__ void ldsm4(uint32_t* r, uint32_t a) {
    asm volatile("ldmatrix.sync.aligned.m8n8.x4.shared.b16 {%0,%1,%2,%3}, [%4];"
                 : "=r"(r[0]), "=r"(r[1]), "=r"(r[2]), "=r"(r[3]) : "r"(a));
}
__device__ __forceinline__ void ldsm4t(uint32_t* r, uint32_t a) {
    asm volatile("ldmatrix.sync.aligned.m8n8.x4.trans.shared.b16 {%0,%1,%2,%3}, [%4];"
                 : "=r"(r[0]), "=r"(r[1]), "=r"(r[2]), "=r"(r[3]) : "r"(a));
}
__device__ __forceinline__ void mma_bf16(float* d, const uint32_t* a, uint32_t b0, uint32_t b1) {
    asm volatile(
        "mma.sync.aligned.m16n8k16.row.col.f32.bf16.bf16.f32 "
        "{%0,%1,%2,%3}, {%4,%5,%6,%7}, {%8,%9}, {%0,%1,%2,%3};"
        : "+f"(d[0]), "+f"(d[1]), "+f"(d[2]), "+f"(d[3])
        : "r"(a[0]), "r"(a[1]), "r"(a[2]), "r"(a[3]), "r"(b0), "r"(b1));
}
__device__ __forceinline__ void mma_f16(float* d, const uint32_t* a, uint32_t b0, uint32_t b1) {
    asm volatile(
        "mma.sync.aligned.m16n8k16.row.col.f32.f16.f16.f32 "
        "{%0,%1,%2,%3}, {%4,%5,%6,%7}, {%8,%9}, {%0,%1,%2,%3};"
        : "+f"(d[0]), "+f"(d[1]), "+f"(d[2]), "+f"(d[3])
        : "r"(a[0]), "r"(a[1]), "r"(a[2]), "r"(a[3]), "r"(b0), "r"(b1));
}

__device__ __forceinline__ void split4(float4 v, __nv_bfloat162* dh,
                                       __nv_bfloat162* dl, int i) {
    __nv_bfloat16 h0 = __float2bfloat16(v.x), h1 = __float2bfloat16(v.y);
    __nv_bfloat16 h2 = __float2bfloat16(v.z), h3 = __float2bfloat16(v.w);
    __nv_bfloat16 l0 = __float2bfloat16(v.x - __bfloat162float(h0));
    __nv_bfloat16 l1 = __float2bfloat16(v.y - __bfloat162float(h1));
    __nv_bfloat16 l2 = __float2bfloat16(v.z - __bfloat162float(h2));
    __nv_bfloat16 l3 = __float2bfloat16(v.w - __bfloat162float(h3));
    dh[2 * i]     = __nv_bfloat162(h0, h1);
    dh[2 * i + 1] = __nv_bfloat162(h2, h3);
    dl[2 * i]     = __nv_bfloat162(l0, l1);
    dl[2 * i + 1] = __nv_bfloat162(l2, l3);
}

__device__ __forceinline__ void cvt_f16_store8(__half2* dst, int i, float4 v) {
    __half2 a = __halves2half2(__float2half_rn(v.x), __float2half_rn(v.y));
    __half2 b = __halves2half2(__float2half_rn(v.z), __float2half_rn(v.w));
    uint2 u;
    u.x = *(uint32_t*)&a;
    u.y = *(uint32_t*)&b;
    *(uint2*)(dst + 2 * i) = u;
}

// ---------------------------------------------------------------------------
// route (blocks 0..7) fused with W1 split (blocks 8..) — both on main stream.
// Routing is bit-exact vs JAX (exact small integers in fp32).
// ---------------------------------------------------------------------------
__global__ void route_w1(const float* __restrict__ z, const float4* __restrict__ W1) {
    int bid = blockIdx.x, t = threadIdx.x;
    if (bid < 8) {
        int i = bid * 256 + t;
        const float* zr = z + (size_t)i * Z_;
        float s = 0.0f;
        #pragma unroll 8
        for (int k = 0; k < Z_; k++)
            s += floorf(fabsf(zr[k]) * 1000.0f);
        g_idx[i] = ((int)s) & (E_ - 1);
    } else {
        int i = (bid - 8) * 256 + t;   // < 262144
        split4(W1[i], (__nv_bfloat162*)g_w1_h, (__nv_bfloat162*)g_w1_l, i);
    }
}

// W2 fp32 -> fp16 convert; own launch (no smem, low regs) on the side stream.
__global__ void w2conv(const float4* __restrict__ W2) {
    const int stride = CONVB * 256;
    __half2* dst = (__half2*)g_w2f;
    int base = blockIdx.x * 256 + threadIdx.x;
    #pragma unroll
    for (int o = 0; o < 3; o++) {
        int i0 = base + (o * 4) * stride;
        float4 v0 = W2[i0];
        float4 v1 = W2[i0 + stride];
        float4 v2 = W2[i0 + 2 * stride];
        float4 v3 = W2[i0 + 3 * stride];
        cvt_f16_store8(dst, i0,              v0);
        cvt_f16_store8(dst, i0 + stride,     v1);
        cvt_f16_store8(dst, i0 + 2 * stride, v2);
        cvt_f16_store8(dst, i0 + 3 * stride, v3);
    }
}

__global__ void scan_scatter() {
    __shared__ int cnt[E_], cur[E_], offs[E_];
    int t = threadIdx.x;
    if (t < E_) { cnt[t] = 0; cur[t] = 0; }
    __syncthreads();
    for (int i = t; i < B_; i += blockDim.x) atomicAdd(&cnt[g_idx[i]], 1);
    __syncthreads();
    if (t == 0) {
        int o = 0, nt = 0;
        g_offsets[0] = 0;
        for (int e = 0; e < E_; e++) {
            int c = cnt[e];
            offs[e] = o;
            for (int r = 0; r < c; r += BM) { g_tile_e[nt] = e; g_tile_r[nt] = r; nt++; }
            o += c;
            g_offsets[e + 1] = o;
        }
        g_num_tiles = nt;
    }
    __syncthreads();
    for (int i = t; i < B_; i += blockDim.x) {
        int e = g_idx[i];
        int pos = offs[e] + atomicAdd(&cur[e], 1);
        g_perm[pos] = i;
    }
}

// z gather + bf16 hi/lo split only (perm-dependent)
__global__ void prep_z(const float4* __restrict__ z4) {
    int idx = blockIdx.x * 256 + threadIdx.x;    // 256 blocks
    int p = idx >> 5, k4 = idx & 31;
    float4 v = z4[(size_t)g_perm[p] * 32 + k4];
    split4(v, (__nv_bfloat162*)g_zg_h, (__nv_bfloat162*)g_zg_l, idx);
}

// ---------------------------------------------------------------------------
// GEMM1 tile: bf16 3-term (z @ W1), relu, fp16 output (perm-order rows)
// ---------------------------------------------------------------------------
__device__ void moe_gemm_tile1(const float* __restrict__ bias, int nblk, int tile,
                               char* smem) {
    const int K = Z_, NTOT = H_;
    const int e      = g_tile_e[tile];
    const int row0   = g_tile_r[tile];
    const int off    = g_offsets[e];
    const int cnt    = g_offsets[e + 1] - off;
    const int mvalid = min(BM, cnt - row0);
    const int n0     = nblk * BN;
    const int arow0  = off + row0;

    const uint32_t sb = smem_u32(smem);
    float* sBias = (float*)(smem + OFF_BIAS);
    const int t = threadIdx.x;
    const int lane = t & 31;
    const int wid = t >> 5;

    if (t < 128) sBias[t] = bias[(size_t)e * NTOT + n0 + t];

    const __nv_bfloat16* BhE = g_w1_h + (size_t)e * NTOT * K;
    const __nv_bfloat16* BlE = g_w1_l + (size_t)e * NTOT * K;
    const int NS = K / BK;

    auto load_stage = [&](int s) {
        const int k0 = s * BK;
        const uint32_t base = sb + (s % NSTG) * STAGE;
        #pragma unroll
        for (int i = 0; i < 2; i++) {
            int idx = t + i * 256;
            int r = idx >> 2, kc = idx & 3;
            uint32_t d = (uint32_t)(r * 80 + kc * 16);
            size_t so = (size_t)(arow0 + r) * K + k0 + kc * 8;
            cp16(base + OFF_AH + d, g_zg_h + so);
            cp16(base + OFF_AL + d, g_zg_l + so);
        }
        #pragma unroll
        for (int i = 0; i < 2; i++) {
            int idx = t + i * 256;
            int kr = idx >> 4, nc = idx & 15;
            uint32_t d = (uint32_t)(kr * 256 + nc * 16) ^ (uint32_t)((kr & 15) << 4);
            size_t so = (size_t)(k0 + kr) * NTOT + n0 + nc * 8;
            cp16(base + OFF_BH + d, BhE + so);
            cp16(base + OFF_BL + d, BlE + so);
        }
        cp_commit();
    };

    const int wm0 = (wid & 3) * 32;
    const int wn0 = (wid >> 2) * 64;

    float acc[2][8][4];
    #pragma unroll
    for (int a = 0; a < 2; a++)
        #pragma unroll
        for (int b = 0; b < 8; b++)
            #pragma unroll
            for (int c = 0; c < 4; c++) acc[a][b][c] = 0.0f;

    load_stage(0);
    load_stage(1);
    load_stage(2);

    for (int s = 0; s < NS; s++) {
        cp_wait2();
        __syncthreads();
        const uint32_t base = sb + (s % NSTG) * STAGE;
        #pragma unroll
        for (int kk = 0; kk < 2; kk++) {
            uint32_t a_h[2][4], a_l[2][4];
            #pragma unroll
            for (int mi = 0; mi < 2; mi++) {
                uint32_t ad = base + OFF_AH +
                    (uint32_t)((wm0 + mi * 16 + (lane & 15)) * 80 + (lane >> 4) * 16 + kk * 32);
                ldsm4(a_h[mi], ad);
                ldsm4(a_l[mi], ad + (OFF_AL - OFF_AH));
            }
            #pragma unroll
            for (int pp = 0; pp < 2; pp++) {
                uint32_t b_h[2][4], b_l[2][4];
                #pragma unroll
                for (int q = 0; q < 2; q++) {
                    int p = pp * 2 + q;
                    uint32_t nb = (uint32_t)((wn0 + p * 16 + (lane >> 4) * 8) * 2);
                    uint32_t bd = base + OFF_BH +
                        (((uint32_t)((kk * 16 + (lane & 15)) * 256) + nb) ^ (uint32_t)((lane & 15) << 4));
                    ldsm4t(b_h[q], bd);
                    ldsm4t(b_l[q], bd + (OFF_BL - OFF_BH));
                }
                #pragma unroll
                for (int mi = 0; mi < 2; mi++)
                    #pragma unroll
                    for (int nq = 0; nq < 4; nq++) {
                        int ni = pp * 4 + nq;
                        int q = nq >> 1, hh = (nq & 1) * 2;
                        mma_bf16(acc[mi][ni], a_h[mi], b_h[q][hh], b_h[q][hh + 1]);
                        mma_bf16(acc[mi][ni], a_h[mi], b_l[q][hh], b_l[q][hh + 1]);
                        mma_bf16(acc[mi][ni], a_l[mi], b_h[q][hh], b_h[q][hh + 1]);
                    }
            }
        }
        __syncthreads();
        if (s + 3 < NS) load_stage(s + 3);
        else cp_commit();
    }

    #pragma unroll
    for (int mi = 0; mi < 2; mi++) {
        #pragma unroll
        for (int half = 0; half < 2; half++) {
            int r = wm0 + mi * 16 + (lane >> 2) + half * 8;
            if (r >= mvalid) continue;
            #pragma unroll
            for (int ni = 0; ni < 8; ni++) {
                int cl = wn0 + ni * 8 + (lane & 3) * 2;
                float v0 = fmaxf(acc[mi][ni][half * 2]     + sBias[cl], 0.0f);
                float v1 = fmaxf(acc[mi][ni][half * 2 + 1] + sBias[cl + 1], 0.0f);
                size_t p = (size_t)(arow0 + r) * NTOT + n0 + cl;
                *(__half2*)(g_hg + p) =
                    __halves2half2(__float2half_rn(v0), __float2half_rn(v1));
            }
        }
    }
}

// ---------------------------------------------------------------------------
// GEMM2 tile: fp16 single-term (h @ W2), bias, fp32 scatter to original rows
// ---------------------------------------------------------------------------
__device__ void moe_gemm_tile2(const float* __restrict__ bias, float* __restrict__ outf,
                               int nblk, int tile, char* smem) {
    const int K = H_, NTOT = O_;
    const int e      = g_tile_e[tile];
    const int row0   = g_tile_r[tile];
    const int off    = g_offsets[e];
    const int cnt    = g_offsets[e + 1] - off;
    const int mvalid = min(BM, cnt - row0);
    const int n0     = nblk * BN;
    const int arow0  = off + row0;

    const uint32_t sb = smem_u32(smem);
    float* sBias = (float*)(smem + F2_BIAS);
    int*   sPerm = (int*)(smem + F2_PERM);

    const int t = threadIdx.x;
    const int lane = t & 31;
    const int wid = t >> 5;

    if (t < 128) {
        sBias[t] = bias[(size_t)e * NTOT + n0 + t];
        sPerm[t] = (t < mvalid) ? g_perm[arow0 + t] : 0;
    }

    const __half* BE = g_w2f + (size_t)e * NTOT * K;
    const int NS = K / BK;

    auto load_stage = [&](int s) {
        const int k0 = s * BK;
        const uint32_t base = sb + (s % NSTG) * F2_STAGE;
        #pragma unroll
        for (int i = 0; i < 2; i++) {               // A: 512 chunks of 16B
            int idx = t + i * 256;
            int r = idx >> 2, kc = idx & 3;
            uint32_t d = (uint32_t)(r * 80 + kc * 16);
            cp16(base + F2_A + d, g_hg + (size_t)(arow0 + r) * K + k0 + kc * 8);
        }
        #pragma unroll
        for (int i = 0; i < 2; i++) {               // B: 512 chunks of 16B
            int idx = t + i * 256;
            int kr = idx >> 4, nc = idx & 15;
            uint32_t d = (uint32_t)(kr * 256 + nc * 16) ^ (uint32_t)((kr & 15) << 4);
            cp16(base + F2_B + d, BE + (size_t)(k0 + kr) * NTOT + n0 + nc * 8);
        }
        cp_commit();
    };

    const int wm0 = (wid & 3) * 32;
    const int wn0 = (wid >> 2) * 64;

    float acc[2][8][4];
    #pragma unroll
    for (int a = 0; a < 2; a++)
        #pragma unroll
        for (int b = 0; b < 8; b++)
            #pragma unroll
            for (int c = 0; c < 4; c++) acc[a][b][c] = 0.0f;

    load_stage(0);
    load_stage(1);
    load_stage(2);

    for (int s = 0; s < NS; s++) {
        cp_wait2();
        __syncthreads();
        const uint32_t base = sb + (s % NSTG) * F2_STAGE;
        #pragma unroll
        for (int kk = 0; kk < 2; kk++) {
            uint32_t a[2][4];
            #pragma unroll
            for (int mi = 0; mi < 2; mi++) {
                uint32_t ad = base + F2_A +
                    (uint32_t)((wm0 + mi * 16 + (lane & 15)) * 80 + (lane >> 4) * 16 + kk * 32);
                ldsm4(a[mi], ad);
            }
            uint32_t b[4][4];
            #pragma unroll
            for (int p = 0; p < 4; p++) {
                uint32_t nb = (uint32_t)((wn0 + p * 16 + (lane >> 4) * 8) * 2);
                uint32_t bd = base + F2_B +
                    (((uint32_t)((kk * 16 + (lane & 15)) * 256) + nb) ^ (uint32_t)((lane & 15) << 4));
                ldsm4t(b[p], bd);
            }
            #pragma unroll
            for (int mi = 0; mi < 2; mi++)
                #pragma unroll
                for (int ni = 0; ni < 8; ni++) {
                    int p = ni >> 1, hh = (ni & 1) * 2;
                    mma_f16(acc[mi][ni], a[mi], b[p][hh], b[p][hh + 1]);
                }
        }
        __syncthreads();
        if (s + 3 < NS) load_stage(s + 3);
        else cp_commit();
    }

    #pragma unroll
    for (int mi = 0; mi < 2; mi++) {
        #pragma unroll
        for (int half = 0; half < 2; half++) {
            int r = wm0 + mi * 16 + (lane >> 2) + half * 8;
            if (r >= mvalid) continue;
            #pragma unroll
            for (int ni = 0; ni < 8; ni++) {
                int cl = wn0 + ni * 8 + (lane & 3) * 2;
                float v0 = acc[mi][ni][half * 2]     + sBias[cl];
                float v1 = acc[mi][ni][half * 2 + 1] + sBias[cl + 1];
                size_t p = (size_t)sPerm[r] * NTOT + n0 + cl;
                *(float2*)(outf + p) = make_float2(v0, v1);
            }
        }
    }
}

// ---------------------------------------------------------------------------
__global__ __launch_bounds__(256, 2)
void moe_mma1(const float* __restrict__ b1) {
    extern __shared__ char smem[];
    int tile = blockIdx.x >> 3;
    if (tile >= g_num_tiles) return;
    moe_gemm_tile1(b1, blockIdx.x & 7, tile, smem);
}

__global__ __launch_bounds__(256, 2)
void moe_mma2(const float* __restrict__ b2, float* __restrict__ out) {
    extern __shared__ char smem[];
    int tile = blockIdx.y;
    if (tile >= g_num_tiles) return;
    moe_gemm_tile2(b2, out, blockIdx.x, tile, smem);
}

// ---------------------------------------------------------------------------
extern "C" void kernel_launch(void* const* d_in, const int* in_sizes, int n_in,
                              void* d_out, int out_size) {
    const float* z  = (const float*)d_in[0];
    const float* W1 = (const float*)d_in[1];
    const float* b1 = (const float*)d_in[2];
    const float* W2 = (const float*)d_in[3];
    const float* b2 = (const float*)d_in[4];
    float* out = (float*)d_out;

    static cudaStream_t s_side = nullptr;
    static cudaEvent_t ev_fork = nullptr, ev_join = nullptr;
    if (!s_side) {
        cudaStreamCreateWithFlags(&s_side, cudaStreamNonBlocking);
        cudaEventCreateWithFlags(&ev_fork, cudaEventDisableTiming);
        cudaEventCreateWithFlags(&ev_join, cudaEventDisableTiming);
        cudaFuncSetAttribute(moe_mma1, cudaFuncAttributeMaxDynamicSharedMemorySize, SMEM_TOTAL);
        cudaFuncSetAttribute(moe_mma2, cudaFuncAttributeMaxDynamicSharedMemorySize, SMEM2_TOTAL);
    }

    // Fork: W2 convert (routing-independent) runs on the side stream at full
    // occupancy, overlapping the routing chain + GEMM1 on the main stream.
    cudaEventRecord(ev_fork, 0);
    cudaStreamWaitEvent(s_side, ev_fork, 0);
    w2conv<<<CONVB, 256, 0, s_side>>>((const float4*)W2);

    route_w1<<<8 + W1_BLOCKS, 256>>>(z, (const float4*)W1);
    scan_scatter<<<1, 1024>>>();
    prep_z<<<256, 256>>>((const float4*)z);
    moe_mma1<<<G1_BLOCKS, 256, SMEM_TOTAL>>>(b1);

    // Join: GEMM2 needs both g_hg (main) and g_w2f (side).
    cudaEventRecord(ev_join, s_side);
    cudaStreamWaitEvent(0, ev_join, 0);
    moe_mma2<<<dim3(O_ / BN, MAXT), 256, SMEM2_TOTAL>>>(b2, out);
}